// round 14
// baseline (speedup 1.0000x reference)
#include <cuda_runtime.h>
#include <cuda_bf16.h>
#include <cuda_fp16.h>
#include <math_constants.h>
#include <cstdint>
#include <cstring>

// Problem constants
#define BATCH 4
#define SLEN  32768
#define C1    128
#define C2    256
#define HID   512
#define L1LEN 16384
#define L2LEN 8192
#define L3LEN 4096
#define VOCAB 2048
#define KCB   4
#define NTOK  (BATCH * KCB * L3LEN)      // 65536

// ------------------- device scratch (device-code references ONLY) -------------------
__device__ __align__(16) float g_conv1[BATCH * C1 * L1LEN];
__device__ __align__(16) float g_conv2[BATCH * C2 * L2LEN];
__device__ __align__(16) float g_feats[BATCH * L3LEN * HID];       // fp32 exact
__device__ __align__(16) float2 g_w2p[(C2 / 128) * (C1 / 8) * 56 * 64];   // packed pairs
__device__ __align__(16) float2 g_w3p[(HID / 128) * (C2 / 8) * 56 * 64];
__device__ __align__(16) __nv_bfloat16 g_fhi[BATCH * L3LEN * HID];
__device__ __align__(16) __nv_bfloat16 g_chi[KCB * VOCAB * HID];
__device__ float g_c2[KCB * VOCAB];
__device__ float g_f2[BATCH * L3LEN];
__device__ float g_cbmax[KCB];
__device__ int   g_tokens[NTOK];
__device__ int   g_cand[NTOK];
__device__ int   g_ncand;

// ==================== helpers ====================
__device__ __forceinline__ uint64_t pkdup(float v) {
    uint64_t r; asm("mov.b64 %0, {%1, %1};" : "=l"(r) : "f"(v)); return r;
}
__device__ __forceinline__ void fma2(uint64_t& c, uint64_t a, uint64_t b) {
    asm("fma.rn.f32x2 %0, %1, %2, %0;" : "+l"(c) : "l"(a), "l"(b));
}
__device__ __forceinline__ float2 upk(uint64_t v) {
    float2 f; asm("mov.b64 {%0, %1}, %2;" : "=f"(f.x), "=f"(f.y) : "l"(v)); return f;
}
__device__ __forceinline__ uint32_t smem_u32(const void* p) {
    uint32_t a;
    asm("{ .reg .u64 t; cvta.to.shared.u64 t, %1; cvt.u32.u64 %0, t; }" : "=r"(a) : "l"(p));
    return a;
}
__device__ __forceinline__ void cp_async16(uint32_t s, const void* g) {
    asm volatile("cp.async.cg.shared.global [%0], [%1], 16;" :: "r"(s), "l"(g) : "memory");
}
__device__ __forceinline__ void cp_async16z(uint32_t s, const void* g, int n) {
    asm volatile("cp.async.cg.shared.global [%0], [%1], 16, %2;" :: "r"(s), "l"(g), "r"(n) : "memory");
}
#define CP_COMMIT() asm volatile("cp.async.commit_group;" ::: "memory")
#define CP_WAIT0()  asm volatile("cp.async.wait_group 0;" ::: "memory")
#define CP_WAIT1()  asm volatile("cp.async.wait_group 1;" ::: "memory")

__device__ __forceinline__ void mma_bf16(float* c, const uint32_t* a, const uint32_t* b0, const uint32_t* b1) {
    asm volatile(
        "mma.sync.aligned.m16n8k16.row.col.f32.bf16.bf16.f32 "
        "{%0,%1,%2,%3}, {%4,%5,%6,%7}, {%8,%9}, {%0,%1,%2,%3};"
        : "+f"(c[0]), "+f"(c[1]), "+f"(c[2]), "+f"(c[3])
        : "r"(a[0]), "r"(a[1]), "r"(a[2]), "r"(a[3]), "r"(*b0), "r"(*b1));
}
__device__ __forceinline__ void ldsm_x4(uint32_t* r, uint32_t addr) {
    asm volatile("ldmatrix.sync.aligned.m8n8.x4.shared.b16 {%0,%1,%2,%3}, [%4];"
                 : "=r"(r[0]), "=r"(r[1]), "=r"(r[2]), "=r"(r[3]) : "r"(addr));
}
__device__ __forceinline__ void upd_min(float& m, float& m2, int& idx, float d, int v) {
    if (d < m)       { m2 = m; m = d; idx = v; }
    else if (d < m2) { m2 = d; }
}
__device__ __forceinline__ void merge_min(float& m, float& m2, int& idx,
                                          float om, float om2, int oidx) {
    if (om < m) { m2 = fminf(m, om2); m = om; idx = oidx; }
    else        { m2 = fminf(m2, om); }
}

// ==================== weight pack: w[co][ci][7] -> [cb][chunk][row56][pair64] ====================
template <int CI, int CO, int STAGE>
__global__ void wpack_kernel(const float* __restrict__ w) {
    float2* wp = (STAGE == 2) ? g_w2p : g_w3p;
    const int TOTAL = (CO / 128) * (CI / 8) * 56 * 64;
    int i = blockIdx.x * 256 + threadIdx.x;
    if (i >= TOTAL) return;
    int p = i & 63;
    int row = (i >> 6) % 56;
    int chunk = ((i >> 6) / 56) % (CI / 8);
    int cb = (i >> 6) / 56 / (CI / 8);
    int ci = chunk * 8 + row / 7;
    int t = row % 7;
    int c_lo = (p < 32) ? p : p + 32;
    int co_lo = cb * 128 + c_lo;
    wp[i] = make_float2(w[((size_t)co_lo * CI + ci) * 7 + t],
                        w[((size_t)(co_lo + 32) * CI + ci) * 7 + t]);
}

// ==================== conv1 ====================
__global__ __launch_bounds__(256) void conv1_fast_kernel(const float* __restrict__ x,
                                                         const float* __restrict__ w,
                                                         const float* __restrict__ bias) {
    __shared__ float a_s[136];
    int tid = threadIdx.x;
    int lane = tid & 31, lg = tid >> 5;
    int l0 = blockIdx.x * 64;
    int b = blockIdx.y;

    for (int p = tid; p < 133; p += 256) {
        int pg = 2 * l0 - 3 + p;
        a_s[p] = (pg >= 0 && pg < SLEN) ? x[(size_t)b * SLEN + pg] : 0.f;
    }
    __syncthreads();

    float wr[4][7], bv[4];
#pragma unroll
    for (int c = 0; c < 4; c++) {
        int ch = lane + 32 * c;
        bv[c] = bias[ch];
#pragma unroll
        for (int t = 0; t < 7; t++) wr[c][t] = w[ch * 7 + t];
    }

    float xv[21];
#pragma unroll
    for (int p = 0; p < 21; p++) xv[p] = a_s[16 * lg + p];

    float acc[4][8];
#pragma unroll
    for (int c = 0; c < 4; c++)
#pragma unroll
        for (int j = 0; j < 8; j++) acc[c][j] = bv[c];
#pragma unroll
    for (int t = 0; t < 7; t++) {
#pragma unroll
        for (int j = 0; j < 8; j++) {
            float xx = xv[2 * j + t];
#pragma unroll
            for (int c = 0; c < 4; c++)
                acc[c][j] = fmaf(wr[c][t], xx, acc[c][j]);
        }
    }
#pragma unroll
    for (int c = 0; c < 4; c++) {
        int ch = lane + 32 * c;
#pragma unroll
        for (int j = 0; j < 8; j++) {
            int l = l0 + lg * 8 + j;
            g_conv1[((size_t)b * C1 + ch) * L1LEN + l] = fmaxf(acc[c][j], 0.f);
        }
    }
}

// ==================== conv2/3: FFMA2 + cp.async double-buffered ====================
#define CV_INSTRIDE 168
#define CV_INSZ (8 * CV_INSTRIDE * 4)       // 5376
#define CV_WSZ  (56 * 64 * 8)               // 28672
#define CV_BUFSZ (CV_INSZ + CV_WSZ)         // 34048
#define CV_SMEM  (2 * CV_BUFSZ)             // 68096

template <int CI, int CO, int LOUT, bool RELU, bool TRANS_OUT, int STAGE>
__global__ __launch_bounds__(256, 3) void conv_fast_kernel(const float* __restrict__ bias) {
    const float*  in = (STAGE == 2) ? g_conv1 : g_conv2;
    const float2* wp = (STAGE == 2) ? g_w2p : g_w3p;
    float*       out = (STAGE == 2) ? g_conv2 : g_feats;

    const int LIN = 2 * LOUT;
    const int NCH = CI / 8;
    extern __shared__ __align__(16) char dsm[];
    uint32_t sb = smem_u32(dsm);

    int tid = threadIdx.x;
    int lane = tid & 31, lg = tid >> 5;
    int l0  = blockIdx.x * 64;
    int cb  = blockIdx.y;
    int b   = blockIdx.z;

    const int gs = 2 * l0 - 16;

    auto stage_chunk = [&](int kc, int s) {
        uint32_t base = sb + s * CV_BUFSZ;
#pragma unroll
        for (int r = 0; r < 2; r++) {
            int i = tid + r * 256;
            if (i < 320) {
                int ci = i / 40, q = i % 40;
                int gf = gs + q * 4;
                int valid = (gf >= 0 && gf + 4 <= LIN) ? 16 : 0;
                const float* src = in + ((size_t)b * CI + kc * 8 + ci) * LIN + (gf < 0 ? 0 : gf);
                cp_async16z(base + ci * (CV_INSTRIDE * 4) + q * 16, src, valid);
            }
        }
        const char* wsrc = (const char*)(wp + ((size_t)cb * NCH + kc) * 3584);
        uint32_t wdst = base + CV_INSZ;
#pragma unroll
        for (int r = 0; r < 7; r++) {
            int i = tid + r * 256;
            cp_async16(wdst + i * 16, wsrc + i * 16);
        }
        CP_COMMIT();
    };

    uint64_t acc2[2][8];
#pragma unroll
    for (int cp = 0; cp < 2; cp++)
#pragma unroll
        for (int j = 0; j < 8; j++) acc2[cp][j] = 0ull;

    stage_chunk(0, 0);

    for (int kc = 0; kc < NCH; kc++) {
        CP_WAIT0();
        __syncthreads();
        if (kc + 1 < NCH) stage_chunk(kc + 1, (kc + 1) & 1);

        const float*  in_s = (const float*)(dsm + (kc & 1) * CV_BUFSZ);
        const float2* w_s  = (const float2*)(dsm + (kc & 1) * CV_BUFSZ + CV_INSZ);

#pragma unroll
        for (int ci = 0; ci < 8; ci++) {
            const float* inrow = in_s + ci * CV_INSTRIDE + 13 + 16 * lg;
            float xvf[21];
#pragma unroll
            for (int p = 0; p < 21; p++) xvf[p] = inrow[p];

#pragma unroll
            for (int t = 0; t < 7; t++) {
                const float2* wrow = w_s + (ci * 7 + t) * 64;
                float2 w0f = wrow[lane];
                float2 w1f = wrow[32 + lane];
                uint64_t w0, w1;
                memcpy(&w0, &w0f, 8);
                memcpy(&w1, &w1f, 8);
#pragma unroll
                for (int j = 0; j < 8; j++) {
                    uint64_t xd = pkdup(xvf[2 * j + t]);
                    fma2(acc2[0][j], w0, xd);
                    fma2(acc2[1][j], w1, xd);
                }
            }
        }
        __syncthreads();
    }

#pragma unroll
    for (int cp = 0; cp < 2; cp++) {
#pragma unroll
        for (int half = 0; half < 2; half++) {
            int c = cp * 2 + half;
            int co = cb * 128 + lane + 32 * c;
            float bv = bias[co];
#pragma unroll
            for (int j = 0; j < 8; j++) {
                float2 a = upk(acc2[cp][j]);
                float r = (half == 0 ? a.x : a.y) + bv;
                if (RELU) r = fmaxf(r, 0.f);
                int l = l0 + lg * 8 + j;
                if (TRANS_OUT) {
                    size_t idx = ((size_t)b * LOUT + l) * CO + co;
                    out[idx] = r;
                    g_fhi[idx] = __float2bfloat16_rn(r);
                } else {
                    out[((size_t)b * CO + co) * LOUT + l] = r;
                }
            }
        }
    }
}

// ==================== codebook prep ====================
__global__ void split_cb_kernel(const float* __restrict__ cb) {
    int i = blockIdx.x * blockDim.x + threadIdx.x;
    if (i >= KCB * VOCAB * HID) return;
    g_chi[i] = __float2bfloat16_rn(cb[i]);
}

__global__ void c2_kernel(const float* __restrict__ cb) {
    int row = blockIdx.x * 8 + (threadIdx.x >> 5);
    int lane = threadIdx.x & 31;
    const float* p = cb + (size_t)row * HID;
    float s = 0.f;
#pragma unroll 4
    for (int h = lane; h < HID; h += 32) {
        float v = p[h];
        s = fmaf(v, v, s);
    }
#pragma unroll
    for (int off = 16; off; off >>= 1)
        s += __shfl_xor_sync(0xffffffffu, s, off);
    if (lane == 0) g_c2[row] = s;
}

__global__ void f2_kernel() {
    int row = blockIdx.x * 8 + (threadIdx.x >> 5);   // BATCH*L3LEN rows
    int lane = threadIdx.x & 31;
    const float* p = g_feats + (size_t)row * HID;
    float s = 0.f;
#pragma unroll 4
    for (int h = lane; h < HID; h += 32) {
        float v = p[h];
        s = fmaf(v, v, s);
    }
#pragma unroll
    for (int off = 16; off; off >>= 1)
        s += __shfl_xor_sync(0xffffffffu, s, off);
    if (lane == 0) g_f2[row] = s;
}

__global__ void cbmax_kernel() {
    __shared__ float red[256];
    int k = blockIdx.x;
    float m = 0.f;
    for (int v = threadIdx.x; v < VOCAB; v += 256)
        m = fmaxf(m, g_c2[k * VOCAB + v]);
    red[threadIdx.x] = m;
    __syncthreads();
    for (int s = 128; s; s >>= 1) {
        if (threadIdx.x < s) red[threadIdx.x] = fmaxf(red[threadIdx.x], red[threadIdx.x + s]);
        __syncthreads();
    }
    if (threadIdx.x == 0) { g_cbmax[k] = sqrtf(red[0]); if (k == 0) g_ncand = 0; }
}

// ==================== fused bf16 GEMM + argmin (128-col v-steps, no spills) ====================
// grid (32 l-tiles, 16 bk). Block 256 (8 warps: wm 0..1 x wn 0..3).
// A tile 128x512 bf16 resident; B streamed 128 v-rows x 64 k per stage, double-buffered.
// Warp tile per v-step: m=64, n=32. acc[4][4][4] = 64 regs (fits; R13 spilled at 128+).
#define FS_ASTRIDE 1040
#define FS_A 0
#define FS_B (128 * FS_ASTRIDE)              // 133120
#define FS_BBUF (128 * 144)                  // 18432
#define FS_C2 (FS_B + 2 * FS_BBUF)           // 169984
#define FS_RED (FS_C2 + 4 * VOCAB)           // 178176
#define FS_TOTAL (FS_RED + 6144)             // 184320

__global__ __launch_bounds__(256, 1) void fused_gemm_argmin_kernel() {
    extern __shared__ __align__(16) char smem[];
    uint32_t sbase = smem_u32(smem);
    float* c2_s = (float*)(smem + FS_C2);
    float* redv = (float*)(smem + FS_RED);
    float* red2 = (float*)(smem + FS_RED + 2048);
    int*   redi = (int*)(smem + FS_RED + 4096);

    const int tid = threadIdx.x;
    const int wid = tid >> 5, lane = tid & 31;
    const int wm = wid >> 2, wn = wid & 3;
    const int g = lane >> 2, t = lane & 3;
    const int lt = blockIdx.x;
    const int bk = blockIdx.y;
    const int b = bk >> 2, k = bk & 3;
    const int l0 = lt * 128;

    const __nv_bfloat16* A  = g_fhi + ((size_t)b * L3LEN + l0) * HID;
    const __nv_bfloat16* Bm = g_chi + (size_t)k * VOCAB * HID;

    // stage A once (8192 x 16B), part of group 0
    for (int i = tid; i < 8192; i += 256) {
        int r = i >> 6, q = i & 63;
        cp_async16(sbase + FS_A + r * FS_ASTRIDE + q * 16, A + (size_t)r * HID + q * 8);
    }
    auto stageB = [&](int m, int s) {       // m = vs*8 + kc
        int vs = m >> 3, kc = m & 7;
#pragma unroll
        for (int it = 0; it < 4; it++) {
            int i = tid + it * 256;
            int r = i >> 3, q = i & 7;
            cp_async16(sbase + FS_B + s * FS_BBUF + r * 144 + q * 16,
                       Bm + (size_t)(vs * 128 + r) * HID + kc * 64 + q * 8);
        }
        CP_COMMIT();
    };
    stageB(0, 0);   // group 0 = A + B(0)

    for (int i = tid; i < VOCAB; i += 256) c2_s[i] = g_c2[k * VOCAB + i];

    const int lrow = (lane & 7) + ((lane >> 3) & 1) * 8;
    const int lcol = (lane >> 4) * 16;
    uint32_t aad[4];
#pragma unroll
    for (int mi = 0; mi < 4; mi++)
        aad[mi] = sbase + FS_A + (wm * 64 + mi * 16 + lrow) * FS_ASTRIDE + lcol;
    uint32_t bad[2][2];
#pragma unroll
    for (int s = 0; s < 2; s++)
#pragma unroll
        for (int j = 0; j < 2; j++)
            bad[s][j] = sbase + FS_B + s * FS_BBUF + (wn * 32 + j * 16 + lrow) * 144 + lcol;

    float minv[8], min2[8];
    int   mini[8];
#pragma unroll
    for (int i = 0; i < 8; i++) { minv[i] = CUDART_INF_F; min2[i] = CUDART_INF_F; mini[i] = 0; }

    for (int vs = 0; vs < 16; vs++) {
        float acc[4][4][4];
#pragma unroll
        for (int mi = 0; mi < 4; mi++)
#pragma unroll
            for (int ni = 0; ni < 4; ni++)
#pragma unroll
                for (int j = 0; j < 4; j++) acc[mi][ni][j] = 0.f;

        for (int kc = 0; kc < 8; kc++) {
            int m = vs * 8 + kc;
            if (m < 127) {
                stageB(m + 1, (m + 1) & 1);
                CP_WAIT1();
            } else {
                CP_WAIT0();
            }
            __syncthreads();
            int s = m & 1;
#pragma unroll
            for (int ks = 0; ks < 4; ks++) {
                uint32_t af[4][4], bfv[2][4];
#pragma unroll
                for (int mi = 0; mi < 4; mi++) ldsm_x4(af[mi], aad[mi] + kc * 128 + ks * 32);
#pragma unroll
                for (int j = 0; j < 2; j++)  ldsm_x4(bfv[j], bad[s][j] + ks * 32);
#pragma unroll
                for (int j = 0; j < 2; j++) {
#pragma unroll
                    for (int mi = 0; mi < 4; mi++) {
                        mma_bf16(acc[mi][2 * j],     af[mi], &bfv[j][0], &bfv[j][2]);
                        mma_bf16(acc[mi][2 * j + 1], af[mi], &bfv[j][1], &bfv[j][3]);
                    }
                }
            }
            __syncthreads();
        }

        // epilogue: dist from registers
#pragma unroll
        for (int mi = 0; mi < 4; mi++) {
#pragma unroll
            for (int half = 0; half < 2; half++) {
                int ridx = mi * 2 + half;
#pragma unroll
                for (int ni = 0; ni < 4; ni++) {
#pragma unroll
                    for (int e = 0; e < 2; e++) {
                        int col = vs * 128 + wn * 32 + ni * 8 + 2 * t + e;
                        float dist = c2_s[col] - 2.f * acc[mi][ni][half * 2 + e];
                        upd_min(minv[ridx], min2[ridx], mini[ridx], dist, col);
                    }
                }
            }
        }
    }

    // reduce over t lanes (4 lanes share each row)
#pragma unroll
    for (int off = 1; off <= 2; off <<= 1) {
#pragma unroll
        for (int i = 0; i < 8; i++) {
            float om  = __shfl_xor_sync(0xffffffffu, minv[i], off);
            float om2 = __shfl_xor_sync(0xffffffffu, min2[i], off);
            int   oi  = __shfl_xor_sync(0xffffffffu, mini[i], off);
            merge_min(minv[i], min2[i], mini[i], om, om2, oi);
        }
    }
    __syncthreads();
    if (t == 0) {
#pragma unroll
        for (int i = 0; i < 8; i++) {
            int rloc = wm * 64 + (i >> 1) * 16 + (i & 1) * 8 + g;
            redv[rloc * 4 + wn] = minv[i];
            red2[rloc * 4 + wn] = min2[i];
            redi[rloc * 4 + wn] = mini[i];
        }
    }
    __syncthreads();

    if (tid < 128) {
        float m  = redv[tid * 4 + 0];
        float m2 = red2[tid * 4 + 0];
        int   mi = redi[tid * 4 + 0];
#pragma unroll
        for (int w = 1; w < 4; w++)
            merge_min(m, m2, mi, redv[tid * 4 + w], red2[tid * 4 + w], redi[tid * 4 + w]);
        int code = bk * L3LEN + l0 + tid;
        g_tokens[code] = mi;
        float TH = 0.009f * sqrtf(g_f2[b * L3LEN + l0 + tid]) * g_cbmax[k] + 1.0f;
        if (m2 - m < TH) {
            int ci = atomicAdd(&g_ncand, 1);
            if (ci < NTOK) g_cand[ci] = code;
        }
    }
}

// ==================== exact fp32 full rescore of flagged tokens ====================
__global__ void rescore_kernel(const float* __restrict__ cb) {
    __shared__ float red_v[256];
    __shared__ int   red_i[256];
    __shared__ float f_s[HID];
    int n = g_ncand;
    if (n > NTOK) n = NTOK;
    for (int ci = blockIdx.x; ci < n; ci += gridDim.x) {
        int code = g_cand[ci];
        int l = code & (L3LEN - 1);
        int bk = code >> 12;
        int k = bk & (KCB - 1);
        int b = bk >> 2;
        __syncthreads();
        for (int h = threadIdx.x; h < HID; h += 256)
            f_s[h] = g_feats[((size_t)b * L3LEN + l) * HID + h];
        __syncthreads();
        const float* C = cb + (size_t)k * VOCAB * HID;
        float bestv = CUDART_INF_F;
        int besti = 0;
        for (int v = threadIdx.x; v < VOCAB; v += 256) {
            const float* c = C + (size_t)v * HID;
            float dot = 0.f;
#pragma unroll 8
            for (int h = 0; h < HID; h++) dot = fmaf(f_s[h], __ldg(c + h), dot);
            float d = g_c2[k * VOCAB + v] - 2.f * dot;
            if (d < bestv) { bestv = d; besti = v; }
        }
        red_v[threadIdx.x] = bestv;
        red_i[threadIdx.x] = besti;
        __syncthreads();
        for (int s = 128; s; s >>= 1) {
            if (threadIdx.x < s) {
                float ov = red_v[threadIdx.x + s];
                int   oi = red_i[threadIdx.x + s];
                if (ov < red_v[threadIdx.x] ||
                    (ov == red_v[threadIdx.x] && oi < red_i[threadIdx.x])) {
                    red_v[threadIdx.x] = ov;
                    red_i[threadIdx.x] = oi;
                }
            }
            __syncthreads();
        }
        if (threadIdx.x == 0) g_tokens[code] = red_i[0];
    }
}

// ==================== outputs ====================
__global__ void emb_kernel(const float* __restrict__ embedding, float* __restrict__ out) {
    int bl = blockIdx.x;
    int b = bl >> 12;
    int l = bl & (L3LEN - 1);
    int t0 = g_tokens[((size_t)b * KCB + 0) * L3LEN + l];
    int t1 = g_tokens[((size_t)b * KCB + 1) * L3LEN + l];
    int t2 = g_tokens[((size_t)b * KCB + 2) * L3LEN + l];
    int t3 = g_tokens[((size_t)b * KCB + 3) * L3LEN + l];
    const float4* e0 = (const float4*)(embedding + (size_t)t0 * HID);
    const float4* e1 = (const float4*)(embedding + (size_t)t1 * HID);
    const float4* e2 = (const float4*)(embedding + (size_t)t2 * HID);
    const float4* e3 = (const float4*)(embedding + (size_t)t3 * HID);
    int h = threadIdx.x;
    float4 v0 = e0[h], v1 = e1[h], v2 = e2[h], v3 = e3[h];
    float4 rr;
    rr.x = 0.25f * (v0.x + v1.x + v2.x + v3.x);
    rr.y = 0.25f * (v0.y + v1.y + v2.y + v3.y);
    rr.z = 0.25f * (v0.z + v1.z + v2.z + v3.z);
    rr.w = 0.25f * (v0.w + v1.w + v2.w + v3.w);
    ((float4*)(out + ((size_t)b * L3LEN + l) * HID))[h] = rr;
}

__global__ void tok2f_kernel(float* __restrict__ out) {
    int i = blockIdx.x * blockDim.x + threadIdx.x;
    if (i < NTOK) out[i] = (float)g_tokens[i];
}

// ==================== launch ====================
extern "C" void kernel_launch(void* const* d_in, const int* in_sizes, int n_in,
                              void* d_out, int out_size) {
    const float* audio = 0; const float* w1 = 0; const float* b1 = 0;
    const float* w2 = 0; const float* b2 = 0; const float* w3 = 0; const float* b3 = 0;
    const float* codebook = 0; const float* embedding = 0;
    for (int i = 0; i < n_in; i++) {
        const float* p = (const float*)d_in[i];
        switch (in_sizes[i]) {
            case BATCH * SLEN:      audio = p; break;
            case C1 * 1 * 7:        w1 = p; break;
            case C1:                b1 = p; break;
            case C2 * C1 * 7:       w2 = p; break;
            case C2:                b2 = p; break;
            case HID * C2 * 7:      w3 = p; break;
            case HID:               b3 = p; break;
            case KCB * VOCAB * HID: codebook = p; break;
            case VOCAB * HID:       embedding = p; break;
            default: break;
        }
    }

    cudaFuncSetAttribute(fused_gemm_argmin_kernel,
                         cudaFuncAttributeMaxDynamicSharedMemorySize, FS_TOTAL);
    cudaFuncSetAttribute(conv_fast_kernel<C1, C2, L2LEN, true, false, 2>,
                         cudaFuncAttributeMaxDynamicSharedMemorySize, CV_SMEM);
    cudaFuncSetAttribute(conv_fast_kernel<C2, HID, L3LEN, false, true, 3>,
                         cudaFuncAttributeMaxDynamicSharedMemorySize, CV_SMEM);

    // order keeps the 4th launch (ncu capture slot) = conv_fast<stage2>
    {
        dim3 grid(L1LEN / 64, BATCH);
        conv1_fast_kernel<<<grid, 256>>>(audio, w1, b1);
    }
    wpack_kernel<C1, C2, 2><<<((C2 / 128) * (C1 / 8) * 3584 + 255) / 256, 256>>>(w2);
    wpack_kernel<C2, HID, 3><<<((HID / 128) * (C2 / 8) * 3584 + 255) / 256, 256>>>(w3);
    {
        dim3 grid(L2LEN / 64, C2 / 128, BATCH);
        conv_fast_kernel<C1, C2, L2LEN, true, false, 2><<<grid, 256, CV_SMEM>>>(b2);
    }
    {
        dim3 grid(L3LEN / 64, HID / 128, BATCH);
        conv_fast_kernel<C2, HID, L3LEN, false, true, 3><<<grid, 256, CV_SMEM>>>(b3);
    }
    split_cb_kernel<<<(KCB * VOCAB * HID) / 256, 256>>>(codebook);
    c2_kernel<<<(KCB * VOCAB) / 8, 256>>>(codebook);
    f2_kernel<<<(BATCH * L3LEN) / 8, 256>>>();
    cbmax_kernel<<<KCB, 256>>>();   // also zeroes g_ncand

    {
        dim3 grid(L3LEN / 128, KCB * BATCH);
        fused_gemm_argmin_kernel<<<grid, 256, FS_TOTAL>>>();
    }
    rescore_kernel<<<1024, 256>>>(codebook);

    const int TOK = NTOK;
    const int EMB = BATCH * L3LEN * HID;
    float* out = (float*)d_out;
    if (out_size >= TOK + EMB) {
        tok2f_kernel<<<(TOK + 255) / 256, 256>>>(out);
        emb_kernel<<<BATCH * L3LEN, 128>>>(embedding, out + TOK);
    } else if (out_size >= EMB) {
        emb_kernel<<<BATCH * L3LEN, 128>>>(embedding, out);
    } else {
        tok2f_kernel<<<(TOK + 255) / 256, 256>>>(out);
    }
}

// round 15
// speedup vs baseline: 41.0641x; 41.0641x over previous
#include <cuda_runtime.h>
#include <cuda_bf16.h>
#include <cuda_fp16.h>
#include <math_constants.h>
#include <cstdint>
#include <cstring>

// Problem constants
#define BATCH 4
#define SLEN  32768
#define C1    128
#define C2    256
#define HID   512
#define L1LEN 16384
#define L2LEN 8192
#define L3LEN 4096
#define VOCAB 2048
#define KCB   4
#define NTOK  (BATCH * KCB * L3LEN)      // 65536

// ------------------- device scratch (device-code references ONLY) -------------------
__device__ __align__(16) float g_conv1[BATCH * C1 * L1LEN];
__device__ __align__(16) float g_conv2[BATCH * C2 * L2LEN];
__device__ __align__(16) float g_feats[BATCH * L3LEN * HID];       // fp32 exact
__device__ __align__(16) float2 g_w2p[(C2 / 128) * (C1 / 8) * 56 * 64];   // packed pairs
__device__ __align__(16) float2 g_w3p[(HID / 128) * (C2 / 8) * 56 * 64];
__device__ __align__(16) __nv_bfloat16 g_fhi[BATCH * L3LEN * HID];
__device__ __align__(16) __nv_bfloat16 g_chi[KCB * VOCAB * HID];
__device__ __align__(16) __half g_cross[(size_t)NTOK * VOCAB];     // fp16 approx dists
__device__ float g_c2[KCB * VOCAB];
__device__ float g_f2[BATCH * L3LEN];
__device__ float g_minv[NTOK];
__device__ float g_cbmax[KCB];
__device__ int   g_tokens[NTOK];
__device__ int   g_cand[NTOK];
__device__ int   g_ncand;

// ==================== helpers ====================
__device__ __forceinline__ uint64_t pkdup(float v) {
    uint64_t r; asm("mov.b64 %0, {%1, %1};" : "=l"(r) : "f"(v)); return r;
}
__device__ __forceinline__ void fma2(uint64_t& c, uint64_t a, uint64_t b) {
    asm("fma.rn.f32x2 %0, %1, %2, %0;" : "+l"(c) : "l"(a), "l"(b));
}
__device__ __forceinline__ float2 upk(uint64_t v) {
    float2 f; asm("mov.b64 {%0, %1}, %2;" : "=f"(f.x), "=f"(f.y) : "l"(v)); return f;
}
__device__ __forceinline__ uint32_t smem_u32(const void* p) {
    uint32_t a;
    asm("{ .reg .u64 t; cvta.to.shared.u64 t, %1; cvt.u32.u64 %0, t; }" : "=r"(a) : "l"(p));
    return a;
}
__device__ __forceinline__ void cp_async16(uint32_t s, const void* g) {
    asm volatile("cp.async.cg.shared.global [%0], [%1], 16;" :: "r"(s), "l"(g) : "memory");
}
__device__ __forceinline__ void cp_async16z(uint32_t s, const void* g, int n) {
    asm volatile("cp.async.cg.shared.global [%0], [%1], 16, %2;" :: "r"(s), "l"(g), "r"(n) : "memory");
}
#define CP_COMMIT() asm volatile("cp.async.commit_group;" ::: "memory")
#define CP_WAIT0()  asm volatile("cp.async.wait_group 0;" ::: "memory")
#define CP_WAIT1()  asm volatile("cp.async.wait_group 1;" ::: "memory")

__device__ __forceinline__ void mma_bf16(float* c, const uint32_t* a, const uint32_t* b0, const uint32_t* b1) {
    asm volatile(
        "mma.sync.aligned.m16n8k16.row.col.f32.bf16.bf16.f32 "
        "{%0,%1,%2,%3}, {%4,%5,%6,%7}, {%8,%9}, {%0,%1,%2,%3};"
        : "+f"(c[0]), "+f"(c[1]), "+f"(c[2]), "+f"(c[3])
        : "r"(a[0]), "r"(a[1]), "r"(a[2]), "r"(a[3]), "r"(*b0), "r"(*b1));
}
__device__ __forceinline__ void ldsm_x4(uint32_t* r, uint32_t addr) {
    asm volatile("ldmatrix.sync.aligned.m8n8.x4.shared.b16 {%0,%1,%2,%3}, [%4];"
                 : "=r"(r[0]), "=r"(r[1]), "=r"(r[2]), "=r"(r[3]) : "r"(addr));
}
__device__ __forceinline__ void upd_min(float& m, float& m2, int& idx, float d, int v) {
    if (d < m)       { m2 = m; m = d; idx = v; }
    else if (d < m2) { m2 = d; }
}
__device__ __forceinline__ void merge_min(float& m, float& m2, int& idx,
                                          float om, float om2, int oidx) {
    if (om < m) { m2 = fminf(m, om2); m = om; idx = oidx; }
    else        { m2 = fminf(m2, om); }
}

// ==================== weight pack ====================
template <int CI, int CO, int STAGE>
__global__ void wpack_kernel(const float* __restrict__ w) {
    float2* wp = (STAGE == 2) ? g_w2p : g_w3p;
    const int TOTAL = (CO / 128) * (CI / 8) * 56 * 64;
    int i = blockIdx.x * 256 + threadIdx.x;
    if (i >= TOTAL) return;
    int p = i & 63;
    int row = (i >> 6) % 56;
    int chunk = ((i >> 6) / 56) % (CI / 8);
    int cb = (i >> 6) / 56 / (CI / 8);
    int ci = chunk * 8 + row / 7;
    int t = row % 7;
    int c_lo = (p < 32) ? p : p + 32;
    int co_lo = cb * 128 + c_lo;
    wp[i] = make_float2(w[((size_t)co_lo * CI + ci) * 7 + t],
                        w[((size_t)(co_lo + 32) * CI + ci) * 7 + t]);
}

// ==================== conv1 ====================
__global__ __launch_bounds__(256) void conv1_fast_kernel(const float* __restrict__ x,
                                                         const float* __restrict__ w,
                                                         const float* __restrict__ bias) {
    __shared__ float a_s[136];
    int tid = threadIdx.x;
    int lane = tid & 31, lg = tid >> 5;
    int l0 = blockIdx.x * 64;
    int b = blockIdx.y;

    for (int p = tid; p < 133; p += 256) {
        int pg = 2 * l0 - 3 + p;
        a_s[p] = (pg >= 0 && pg < SLEN) ? x[(size_t)b * SLEN + pg] : 0.f;
    }
    __syncthreads();

    float wr[4][7], bv[4];
#pragma unroll
    for (int c = 0; c < 4; c++) {
        int ch = lane + 32 * c;
        bv[c] = bias[ch];
#pragma unroll
        for (int t = 0; t < 7; t++) wr[c][t] = w[ch * 7 + t];
    }

    float xv[21];
#pragma unroll
    for (int p = 0; p < 21; p++) xv[p] = a_s[16 * lg + p];

    float acc[4][8];
#pragma unroll
    for (int c = 0; c < 4; c++)
#pragma unroll
        for (int j = 0; j < 8; j++) acc[c][j] = bv[c];
#pragma unroll
    for (int t = 0; t < 7; t++) {
#pragma unroll
        for (int j = 0; j < 8; j++) {
            float xx = xv[2 * j + t];
#pragma unroll
            for (int c = 0; c < 4; c++)
                acc[c][j] = fmaf(wr[c][t], xx, acc[c][j]);
        }
    }
#pragma unroll
    for (int c = 0; c < 4; c++) {
        int ch = lane + 32 * c;
#pragma unroll
        for (int j = 0; j < 8; j++) {
            int l = l0 + lg * 8 + j;
            g_conv1[((size_t)b * C1 + ch) * L1LEN + l] = fmaxf(acc[c][j], 0.f);
        }
    }
}

// ==================== conv2/3: FFMA2 + cp.async double-buffered ====================
#define CV_INSTRIDE 168
#define CV_INSZ (8 * CV_INSTRIDE * 4)       // 5376
#define CV_WSZ  (56 * 64 * 8)               // 28672
#define CV_BUFSZ (CV_INSZ + CV_WSZ)         // 34048
#define CV_SMEM  (2 * CV_BUFSZ)             // 68096

template <int CI, int CO, int LOUT, bool RELU, bool TRANS_OUT, int STAGE>
__global__ __launch_bounds__(256, 3) void conv_fast_kernel(const float* __restrict__ bias) {
    const float*  in = (STAGE == 2) ? g_conv1 : g_conv2;
    const float2* wp = (STAGE == 2) ? g_w2p : g_w3p;
    float*       out = (STAGE == 2) ? g_conv2 : g_feats;

    const int LIN = 2 * LOUT;
    const int NCH = CI / 8;
    extern __shared__ __align__(16) char dsm[];
    uint32_t sb = smem_u32(dsm);

    int tid = threadIdx.x;
    int lane = tid & 31, lg = tid >> 5;
    int l0  = blockIdx.x * 64;
    int cb  = blockIdx.y;
    int b   = blockIdx.z;

    const int gs = 2 * l0 - 16;

    auto stage_chunk = [&](int kc, int s) {
        uint32_t base = sb + s * CV_BUFSZ;
#pragma unroll
        for (int r = 0; r < 2; r++) {
            int i = tid + r * 256;
            if (i < 320) {
                int ci = i / 40, q = i % 40;
                int gf = gs + q * 4;
                int valid = (gf >= 0 && gf + 4 <= LIN) ? 16 : 0;
                const float* src = in + ((size_t)b * CI + kc * 8 + ci) * LIN + (gf < 0 ? 0 : gf);
                cp_async16z(base + ci * (CV_INSTRIDE * 4) + q * 16, src, valid);
            }
        }
        const char* wsrc = (const char*)(wp + ((size_t)cb * NCH + kc) * 3584);
        uint32_t wdst = base + CV_INSZ;
#pragma unroll
        for (int r = 0; r < 7; r++) {
            int i = tid + r * 256;
            cp_async16(wdst + i * 16, wsrc + i * 16);
        }
        CP_COMMIT();
    };

    uint64_t acc2[2][8];
#pragma unroll
    for (int cp = 0; cp < 2; cp++)
#pragma unroll
        for (int j = 0; j < 8; j++) acc2[cp][j] = 0ull;

    stage_chunk(0, 0);

    for (int kc = 0; kc < NCH; kc++) {
        CP_WAIT0();
        __syncthreads();
        if (kc + 1 < NCH) stage_chunk(kc + 1, (kc + 1) & 1);

        const float*  in_s = (const float*)(dsm + (kc & 1) * CV_BUFSZ);
        const float2* w_s  = (const float2*)(dsm + (kc & 1) * CV_BUFSZ + CV_INSZ);

#pragma unroll
        for (int ci = 0; ci < 8; ci++) {
            const float* inrow = in_s + ci * CV_INSTRIDE + 13 + 16 * lg;
            float xvf[21];
#pragma unroll
            for (int p = 0; p < 21; p++) xvf[p] = inrow[p];

#pragma unroll
            for (int t = 0; t < 7; t++) {
                const float2* wrow = w_s + (ci * 7 + t) * 64;
                float2 w0f = wrow[lane];
                float2 w1f = wrow[32 + lane];
                uint64_t w0, w1;
                memcpy(&w0, &w0f, 8);
                memcpy(&w1, &w1f, 8);
#pragma unroll
                for (int j = 0; j < 8; j++) {
                    uint64_t xd = pkdup(xvf[2 * j + t]);
                    fma2(acc2[0][j], w0, xd);
                    fma2(acc2[1][j], w1, xd);
                }
            }
        }
        __syncthreads();
    }

#pragma unroll
    for (int cp = 0; cp < 2; cp++) {
#pragma unroll
        for (int half = 0; half < 2; half++) {
            int c = cp * 2 + half;
            int co = cb * 128 + lane + 32 * c;
            float bv = bias[co];
#pragma unroll
            for (int j = 0; j < 8; j++) {
                float2 a = upk(acc2[cp][j]);
                float r = (half == 0 ? a.x : a.y) + bv;
                if (RELU) r = fmaxf(r, 0.f);
                int l = l0 + lg * 8 + j;
                if (TRANS_OUT) {
                    size_t idx = ((size_t)b * LOUT + l) * CO + co;
                    out[idx] = r;
                    g_fhi[idx] = __float2bfloat16_rn(r);
                } else {
                    out[((size_t)b * CO + co) * LOUT + l] = r;
                }
            }
        }
    }
}

// ==================== codebook prep ====================
__global__ void split_cb_kernel(const float* __restrict__ cb) {
    int i = blockIdx.x * blockDim.x + threadIdx.x;
    if (i >= KCB * VOCAB * HID) return;
    g_chi[i] = __float2bfloat16_rn(cb[i]);
}

__global__ void c2_kernel(const float* __restrict__ cb) {
    int row = blockIdx.x * 8 + (threadIdx.x >> 5);
    int lane = threadIdx.x & 31;
    const float* p = cb + (size_t)row * HID;
    float s = 0.f;
#pragma unroll 4
    for (int h = lane; h < HID; h += 32) {
        float v = p[h];
        s = fmaf(v, v, s);
    }
#pragma unroll
    for (int off = 16; off; off >>= 1)
        s += __shfl_xor_sync(0xffffffffu, s, off);
    if (lane == 0) g_c2[row] = s;
}

__global__ void f2_kernel() {
    int row = blockIdx.x * 8 + (threadIdx.x >> 5);
    int lane = threadIdx.x & 31;
    const float* p = g_feats + (size_t)row * HID;
    float s = 0.f;
#pragma unroll 4
    for (int h = lane; h < HID; h += 32) {
        float v = p[h];
        s = fmaf(v, v, s);
    }
#pragma unroll
    for (int off = 16; off; off >>= 1)
        s += __shfl_xor_sync(0xffffffffu, s, off);
    if (lane == 0) g_f2[row] = s;
}

__global__ void cbmax_kernel() {
    __shared__ float red[256];
    int k = blockIdx.x;
    float m = 0.f;
    for (int v = threadIdx.x; v < VOCAB; v += 256)
        m = fmaxf(m, g_c2[k * VOCAB + v]);
    red[threadIdx.x] = m;
    __syncthreads();
    for (int s = 128; s; s >>= 1) {
        if (threadIdx.x < s) red[threadIdx.x] = fmaxf(red[threadIdx.x], red[threadIdx.x + s]);
        __syncthreads();
    }
    if (threadIdx.x == 0) { g_cbmax[k] = sqrtf(red[0]); if (k == 0) g_ncand = 0; }
}

// ==================== fused bf16 GEMM + argmin (+ fp16 dist dump) ====================
#define FS_ASTRIDE 1040
#define FS_A 0
#define FS_B (128 * FS_ASTRIDE)              // 133120
#define FS_BBUF (128 * 144)                  // 18432
#define FS_C2 (FS_B + 2 * FS_BBUF)           // 169984
#define FS_RED (FS_C2 + 4 * VOCAB)           // 178176
#define FS_TOTAL (FS_RED + 6144)             // 184320

__global__ __launch_bounds__(256, 1) void fused_gemm_argmin_kernel() {
    extern __shared__ __align__(16) char smem[];
    uint32_t sbase = smem_u32(smem);
    float* c2_s = (float*)(smem + FS_C2);
    float* redv = (float*)(smem + FS_RED);
    float* red2 = (float*)(smem + FS_RED + 2048);
    int*   redi = (int*)(smem + FS_RED + 4096);

    const int tid = threadIdx.x;
    const int wid = tid >> 5, lane = tid & 31;
    const int wm = wid >> 2, wn = wid & 3;
    const int g = lane >> 2, t = lane & 3;
    const int lt = blockIdx.x;
    const int bk = blockIdx.y;
    const int b = bk >> 2, k = bk & 3;
    const int l0 = lt * 128;

    const __nv_bfloat16* A  = g_fhi + ((size_t)b * L3LEN + l0) * HID;
    const __nv_bfloat16* Bm = g_chi + (size_t)k * VOCAB * HID;

    for (int i = tid; i < 8192; i += 256) {
        int r = i >> 6, q = i & 63;
        cp_async16(sbase + FS_A + r * FS_ASTRIDE + q * 16, A + (size_t)r * HID + q * 8);
    }
    auto stageB = [&](int m, int s) {       // m = vs*8 + kc
        int vs = m >> 3, kc = m & 7;
#pragma unroll
        for (int it = 0; it < 4; it++) {
            int i = tid + it * 256;
            int r = i >> 3, q = i & 7;
            cp_async16(sbase + FS_B + s * FS_BBUF + r * 144 + q * 16,
                       Bm + (size_t)(vs * 128 + r) * HID + kc * 64 + q * 8);
        }
        CP_COMMIT();
    };
    stageB(0, 0);

    for (int i = tid; i < VOCAB; i += 256) c2_s[i] = g_c2[k * VOCAB + i];

    const int lrow = (lane & 7) + ((lane >> 3) & 1) * 8;
    const int lcol = (lane >> 4) * 16;
    uint32_t aad[4];
#pragma unroll
    for (int mi = 0; mi < 4; mi++)
        aad[mi] = sbase + FS_A + (wm * 64 + mi * 16 + lrow) * FS_ASTRIDE + lcol;
    uint32_t bad[2][2];
#pragma unroll
    for (int s = 0; s < 2; s++)
#pragma unroll
        for (int j = 0; j < 2; j++)
            bad[s][j] = sbase + FS_B + s * FS_BBUF + (wn * 32 + j * 16 + lrow) * 144 + lcol;

    float minv[8], min2[8];
    int   mini[8];
#pragma unroll
    for (int i = 0; i < 8; i++) { minv[i] = CUDART_INF_F; min2[i] = CUDART_INF_F; mini[i] = 0; }

    for (int vs = 0; vs < 16; vs++) {
        float acc[4][4][4];
#pragma unroll
        for (int mi = 0; mi < 4; mi++)
#pragma unroll
            for (int ni = 0; ni < 4; ni++)
#pragma unroll
                for (int j = 0; j < 4; j++) acc[mi][ni][j] = 0.f;

        for (int kc = 0; kc < 8; kc++) {
            int m = vs * 8 + kc;
            if (m < 127) {
                stageB(m + 1, (m + 1) & 1);
                CP_WAIT1();
            } else {
                CP_WAIT0();
            }
            __syncthreads();
            int s = m & 1;
#pragma unroll
            for (int ks = 0; ks < 4; ks++) {
                uint32_t af[4][4], bfv[2][4];
#pragma unroll
                for (int mi = 0; mi < 4; mi++) ldsm_x4(af[mi], aad[mi] + kc * 128 + ks * 32);
#pragma unroll
                for (int j = 0; j < 2; j++)  ldsm_x4(bfv[j], bad[s][j] + ks * 32);
#pragma unroll
                for (int j = 0; j < 2; j++) {
#pragma unroll
                    for (int mi = 0; mi < 4; mi++) {
                        mma_bf16(acc[mi][2 * j],     af[mi], &bfv[j][0], &bfv[j][2]);
                        mma_bf16(acc[mi][2 * j + 1], af[mi], &bfv[j][1], &bfv[j][3]);
                    }
                }
            }
            __syncthreads();
        }

        // epilogue: dist from registers -> min tracking + fp16 dump
#pragma unroll
        for (int mi = 0; mi < 4; mi++) {
#pragma unroll
            for (int half = 0; half < 2; half++) {
                int ridx = mi * 2 + half;
                int row = wm * 64 + mi * 16 + half * 8 + g;
                __half* crow = (__half*)g_cross + ((size_t)bk * L3LEN + l0 + row) * VOCAB;
#pragma unroll
                for (int ni = 0; ni < 4; ni++) {
                    int col0 = vs * 128 + wn * 32 + ni * 8 + 2 * t;
                    float d0 = c2_s[col0]     - 2.f * acc[mi][ni][half * 2 + 0];
                    float d1 = c2_s[col0 + 1] - 2.f * acc[mi][ni][half * 2 + 1];
                    upd_min(minv[ridx], min2[ridx], mini[ridx], d0, col0);
                    upd_min(minv[ridx], min2[ridx], mini[ridx], d1, col0 + 1);
                    *(__half2*)(crow + col0) = __floats2half2_rn(d0, d1);
                }
            }
        }
    }

    // reduce over t lanes (4 lanes share each row)
#pragma unroll
    for (int off = 1; off <= 2; off <<= 1) {
#pragma unroll
        for (int i = 0; i < 8; i++) {
            float om  = __shfl_xor_sync(0xffffffffu, minv[i], off);
            float om2 = __shfl_xor_sync(0xffffffffu, min2[i], off);
            int   oi  = __shfl_xor_sync(0xffffffffu, mini[i], off);
            merge_min(minv[i], min2[i], mini[i], om, om2, oi);
        }
    }
    __syncthreads();
    if (t == 0) {
#pragma unroll
        for (int i = 0; i < 8; i++) {
            int rloc = wm * 64 + (i >> 1) * 16 + (i & 1) * 8 + g;
            redv[rloc * 4 + wn] = minv[i];
            red2[rloc * 4 + wn] = min2[i];
            redi[rloc * 4 + wn] = mini[i];
        }
    }
    __syncthreads();

    if (tid < 128) {
        float m  = redv[tid * 4 + 0];
        float m2 = red2[tid * 4 + 0];
        int   mi = redi[tid * 4 + 0];
#pragma unroll
        for (int w = 1; w < 4; w++)
            merge_min(m, m2, mi, redv[tid * 4 + w], red2[tid * 4 + w], redi[tid * 4 + w]);
        int code = bk * L3LEN + l0 + tid;
        g_tokens[code] = mi;
        g_minv[code] = m;
        float TH = 0.009f * sqrtf(g_f2[b * L3LEN + l0 + tid]) * g_cbmax[k] + 1.0f;
        if (m2 - m < TH) {
            int ci = atomicAdd(&g_ncand, 1);
            if (ci < NTOK) g_cand[ci] = code;
        }
    }
}

// ==================== bounded exact rescore: warp per flagged token ====================
__global__ __launch_bounds__(256) void rescore_kernel(const float* __restrict__ cb) {
    int n = g_ncand;
    if (n > NTOK) n = NTOK;
    int lane = threadIdx.x & 31;
    int wid = threadIdx.x >> 5;
    for (int ci = blockIdx.x * 8 + wid; ci < n; ci += gridDim.x * 8) {
        int code = g_cand[ci];
        int l = code & (L3LEN - 1);
        int bk = code >> 12;
        int k = bk & (KCB - 1);
        int b = bk >> 2;
        const __half2* crow2 = (const __half2*)(g_cross + (size_t)code * VOCAB);
        float thr = g_minv[code] +
                    0.009f * sqrtf(g_f2[b * L3LEN + l]) * g_cbmax[k] + 1.0f;

        const float* f = g_feats + ((size_t)b * L3LEN + l) * HID;
        float fr[16];
#pragma unroll
        for (int j = 0; j < 16; j++) fr[j] = f[j * 32 + lane];

        float bestd = CUDART_INF_F;
        int besti = VOCAB;
        for (int i = 0; i < 32; i++) {
            __half2 h = crow2[i * 32 + lane];
            float d0 = __low2float(h);
            float d1 = __high2float(h);
            unsigned m0 = __ballot_sync(0xffffffffu, d0 <= thr);
            unsigned m1 = __ballot_sync(0xffffffffu, d1 <= thr);
            while (m0 | m1) {
                int s0 = m0 ? (__ffs(m0) - 1) : 33;
                int s1 = m1 ? (__ffs(m1) - 1) : 33;
                int vc;
                if (s0 <= s1) { vc = i * 64 + s0 * 2;     m0 &= m0 - 1; }
                else          { vc = i * 64 + s1 * 2 + 1; m1 &= m1 - 1; }
                const float* c = cb + ((size_t)k * VOCAB + vc) * HID;
                float dot = 0.f;
#pragma unroll
                for (int j = 0; j < 16; j++)
                    dot = fmaf(fr[j], c[j * 32 + lane], dot);
#pragma unroll
                for (int off = 16; off; off >>= 1)
                    dot += __shfl_xor_sync(0xffffffffu, dot, off);
                float de = __ldg(g_c2 + k * VOCAB + vc) - 2.f * dot;
                if (de < bestd || (de == bestd && vc < besti)) { bestd = de; besti = vc; }
            }
        }
        if (lane == 0) g_tokens[code] = besti;
    }
}

// ==================== outputs ====================
__global__ void emb_kernel(const float* __restrict__ embedding, float* __restrict__ out) {
    int bl = blockIdx.x;
    int b = bl >> 12;
    int l = bl & (L3LEN - 1);
    int t0 = g_tokens[((size_t)b * KCB + 0) * L3LEN + l];
    int t1 = g_tokens[((size_t)b * KCB + 1) * L3LEN + l];
    int t2 = g_tokens[((size_t)b * KCB + 2) * L3LEN + l];
    int t3 = g_tokens[((size_t)b * KCB + 3) * L3LEN + l];
    const float4* e0 = (const float4*)(embedding + (size_t)t0 * HID);
    const float4* e1 = (const float4*)(embedding + (size_t)t1 * HID);
    const float4* e2 = (const float4*)(embedding + (size_t)t2 * HID);
    const float4* e3 = (const float4*)(embedding + (size_t)t3 * HID);
    int h = threadIdx.x;
    float4 v0 = e0[h], v1 = e1[h], v2 = e2[h], v3 = e3[h];
    float4 rr;
    rr.x = 0.25f * (v0.x + v1.x + v2.x + v3.x);
    rr.y = 0.25f * (v0.y + v1.y + v2.y + v3.y);
    rr.z = 0.25f * (v0.z + v1.z + v2.z + v3.z);
    rr.w = 0.25f * (v0.w + v1.w + v2.w + v3.w);
    ((float4*)(out + ((size_t)b * L3LEN + l) * HID))[h] = rr;
}

__global__ void tok2f_kernel(float* __restrict__ out) {
    int i = blockIdx.x * blockDim.x + threadIdx.x;
    if (i < NTOK) out[i] = (float)g_tokens[i];
}

// ==================== launch ====================
extern "C" void kernel_launch(void* const* d_in, const int* in_sizes, int n_in,
                              void* d_out, int out_size) {
    const float* audio = 0; const float* w1 = 0; const float* b1 = 0;
    const float* w2 = 0; const float* b2 = 0; const float* w3 = 0; const float* b3 = 0;
    const float* codebook = 0; const float* embedding = 0;
    for (int i = 0; i < n_in; i++) {
        const float* p = (const float*)d_in[i];
        switch (in_sizes[i]) {
            case BATCH * SLEN:      audio = p; break;
            case C1 * 1 * 7:        w1 = p; break;
            case C1:                b1 = p; break;
            case C2 * C1 * 7:       w2 = p; break;
            case C2:                b2 = p; break;
            case HID * C2 * 7:      w3 = p; break;
            case HID:               b3 = p; break;
            case KCB * VOCAB * HID: codebook = p; break;
            case VOCAB * HID:       embedding = p; break;
            default: break;
        }
    }

    cudaFuncSetAttribute(fused_gemm_argmin_kernel,
                         cudaFuncAttributeMaxDynamicSharedMemorySize, FS_TOTAL);
    cudaFuncSetAttribute(conv_fast_kernel<C1, C2, L2LEN, true, false, 2>,
                         cudaFuncAttributeMaxDynamicSharedMemorySize, CV_SMEM);
    cudaFuncSetAttribute(conv_fast_kernel<C2, HID, L3LEN, false, true, 3>,
                         cudaFuncAttributeMaxDynamicSharedMemorySize, CV_SMEM);

    // order keeps the 4th launch (ncu capture slot) = conv_fast<stage2>
    {
        dim3 grid(L1LEN / 64, BATCH);
        conv1_fast_kernel<<<grid, 256>>>(audio, w1, b1);
    }
    wpack_kernel<C1, C2, 2><<<((C2 / 128) * (C1 / 8) * 3584 + 255) / 256, 256>>>(w2);
    wpack_kernel<C2, HID, 3><<<((HID / 128) * (C2 / 8) * 3584 + 255) / 256, 256>>>(w3);
    {
        dim3 grid(L2LEN / 64, C2 / 128, BATCH);
        conv_fast_kernel<C1, C2, L2LEN, true, false, 2><<<grid, 256, CV_SMEM>>>(b2);
    }
    {
        dim3 grid(L3LEN / 64, HID / 128, BATCH);
        conv_fast_kernel<C2, HID, L3LEN, false, true, 3><<<grid, 256, CV_SMEM>>>(b3);
    }
    split_cb_kernel<<<(KCB * VOCAB * HID) / 256, 256>>>(codebook);
    c2_kernel<<<(KCB * VOCAB) / 8, 256>>>(codebook);
    f2_kernel<<<(BATCH * L3LEN) / 8, 256>>>();
    cbmax_kernel<<<KCB, 256>>>();   // also zeroes g_ncand

    {
        dim3 grid(L3LEN / 128, KCB * BATCH);
        fused_gemm_argmin_kernel<<<grid, 256, FS_TOTAL>>>();
    }
    rescore_kernel<<<512, 256>>>(codebook);

    const int TOK = NTOK;
    const int EMB = BATCH * L3LEN * HID;
    float* out = (float*)d_out;
    if (out_size >= TOK + EMB) {
        tok2f_kernel<<<(TOK + 255) / 256, 256>>>(out);
        emb_kernel<<<BATCH * L3LEN, 128>>>(embedding, out + TOK);
    } else if (out_size >= EMB) {
        emb_kernel<<<BATCH * L3LEN, 128>>>(embedding, out);
    } else {
        tok2f_kernel<<<(TOK + 255) / 256, 256>>>(out);
    }
}

// round 16
// speedup vs baseline: 46.3293x; 1.1282x over previous
#include <cuda_runtime.h>
#include <cuda_bf16.h>
#include <cuda_fp16.h>
#include <math_constants.h>
#include <cstdint>
#include <cstring>

// Problem constants
#define BATCH 4
#define SLEN  32768
#define C1    128
#define C2    256
#define HID   512
#define L1LEN 16384
#define L2LEN 8192
#define L3LEN 4096
#define VOCAB 2048
#define KCB   4
#define NTOK  (BATCH * KCB * L3LEN)      // 65536

// ------------------- device scratch (device-code references ONLY) -------------------
__device__ __align__(16) float g_conv1[BATCH * C1 * L1LEN];
__device__ __align__(16) float g_conv2[BATCH * C2 * L2LEN];
__device__ __align__(16) float g_feats[BATCH * L3LEN * HID];       // fp32 exact
__device__ __align__(16) float2 g_w2p[(C2 / 128) * (C1 / 8) * 56 * 64];
__device__ __align__(16) float2 g_w3p[(HID / 128) * (C2 / 8) * 56 * 64];
__device__ __align__(16) __nv_bfloat16 g_fhi[BATCH * L3LEN * HID];
__device__ __align__(16) __nv_bfloat16 g_chi[KCB * VOCAB * HID];
__device__ __align__(16) __half g_dist[(size_t)NTOK * VOCAB];      // fp16 approx dists
__device__ float g_c2[KCB * VOCAB];
__device__ float g_f2[BATCH * L3LEN];
__device__ float g_cbmax[KCB];
__device__ int   g_tokens[NTOK];

// ==================== helpers ====================
__device__ __forceinline__ uint64_t pkdup(float v) {
    uint64_t r; asm("mov.b64 %0, {%1, %1};" : "=l"(r) : "f"(v)); return r;
}
__device__ __forceinline__ void fma2(uint64_t& c, uint64_t a, uint64_t b) {
    asm("fma.rn.f32x2 %0, %1, %2, %0;" : "+l"(c) : "l"(a), "l"(b));
}
__device__ __forceinline__ float2 upk(uint64_t v) {
    float2 f; asm("mov.b64 {%0, %1}, %2;" : "=f"(f.x), "=f"(f.y) : "l"(v)); return f;
}
__device__ __forceinline__ uint32_t smem_u32(const void* p) {
    uint32_t a;
    asm("{ .reg .u64 t; cvta.to.shared.u64 t, %1; cvt.u32.u64 %0, t; }" : "=r"(a) : "l"(p));
    return a;
}
__device__ __forceinline__ void cp_async16(uint32_t s, const void* g) {
    asm volatile("cp.async.cg.shared.global [%0], [%1], 16;" :: "r"(s), "l"(g) : "memory");
}
__device__ __forceinline__ void cp_async16z(uint32_t s, const void* g, int n) {
    asm volatile("cp.async.cg.shared.global [%0], [%1], 16, %2;" :: "r"(s), "l"(g), "r"(n) : "memory");
}
#define CP_COMMIT() asm volatile("cp.async.commit_group;" ::: "memory")
#define CP_WAIT0()  asm volatile("cp.async.wait_group 0;" ::: "memory")
#define CP_WAIT1()  asm volatile("cp.async.wait_group 1;" ::: "memory")

__device__ __forceinline__ void mma_bf16(float* c, const uint32_t* a, const uint32_t* b0, const uint32_t* b1) {
    asm volatile(
        "mma.sync.aligned.m16n8k16.row.col.f32.bf16.bf16.f32 "
        "{%0,%1,%2,%3}, {%4,%5,%6,%7}, {%8,%9}, {%0,%1,%2,%3};"
        : "+f"(c[0]), "+f"(c[1]), "+f"(c[2]), "+f"(c[3])
        : "r"(a[0]), "r"(a[1]), "r"(a[2]), "r"(a[3]), "r"(*b0), "r"(*b1));
}
__device__ __forceinline__ void ldsm_x4(uint32_t* r, uint32_t addr) {
    asm volatile("ldmatrix.sync.aligned.m8n8.x4.shared.b16 {%0,%1,%2,%3}, [%4];"
                 : "=r"(r[0]), "=r"(r[1]), "=r"(r[2]), "=r"(r[3]) : "r"(addr));
}
__device__ __forceinline__ void upd_min(float& m, float& m2, int& idx, float d, int v) {
    if (d < m)       { m2 = m; m = d; idx = v; }
    else if (d < m2) { m2 = d; }
}
__device__ __forceinline__ void merge_min(float& m, float& m2, int& idx,
                                          float om, float om2, int oidx) {
    if (om < m || (om == m && oidx < idx)) { m2 = fminf(m, om2); m = om; idx = oidx; }
    else                                   { m2 = fminf(m2, om); }
}

// ==================== weight pack ====================
template <int CI, int CO, int STAGE>
__global__ void wpack_kernel(const float* __restrict__ w) {
    float2* wp = (STAGE == 2) ? g_w2p : g_w3p;
    const int TOTAL = (CO / 128) * (CI / 8) * 56 * 64;
    int i = blockIdx.x * 256 + threadIdx.x;
    if (i >= TOTAL) return;
    int p = i & 63;
    int row = (i >> 6) % 56;
    int chunk = ((i >> 6) / 56) % (CI / 8);
    int cb = (i >> 6) / 56 / (CI / 8);
    int ci = chunk * 8 + row / 7;
    int t = row % 7;
    int c_lo = (p < 32) ? p : p + 32;
    int co_lo = cb * 128 + c_lo;
    wp[i] = make_float2(w[((size_t)co_lo * CI + ci) * 7 + t],
                        w[((size_t)(co_lo + 32) * CI + ci) * 7 + t]);
}

// ==================== conv1 ====================
__global__ __launch_bounds__(256) void conv1_fast_kernel(const float* __restrict__ x,
                                                         const float* __restrict__ w,
                                                         const float* __restrict__ bias) {
    __shared__ float a_s[136];
    int tid = threadIdx.x;
    int lane = tid & 31, lg = tid >> 5;
    int l0 = blockIdx.x * 64;
    int b = blockIdx.y;

    for (int p = tid; p < 133; p += 256) {
        int pg = 2 * l0 - 3 + p;
        a_s[p] = (pg >= 0 && pg < SLEN) ? x[(size_t)b * SLEN + pg] : 0.f;
    }
    __syncthreads();

    float wr[4][7], bv[4];
#pragma unroll
    for (int c = 0; c < 4; c++) {
        int ch = lane + 32 * c;
        bv[c] = bias[ch];
#pragma unroll
        for (int t = 0; t < 7; t++) wr[c][t] = w[ch * 7 + t];
    }

    float xv[21];
#pragma unroll
    for (int p = 0; p < 21; p++) xv[p] = a_s[16 * lg + p];

    float acc[4][8];
#pragma unroll
    for (int c = 0; c < 4; c++)
#pragma unroll
        for (int j = 0; j < 8; j++) acc[c][j] = bv[c];
#pragma unroll
    for (int t = 0; t < 7; t++) {
#pragma unroll
        for (int j = 0; j < 8; j++) {
            float xx = xv[2 * j + t];
#pragma unroll
            for (int c = 0; c < 4; c++)
                acc[c][j] = fmaf(wr[c][t], xx, acc[c][j]);
        }
    }
#pragma unroll
    for (int c = 0; c < 4; c++) {
        int ch = lane + 32 * c;
#pragma unroll
        for (int j = 0; j < 8; j++) {
            int l = l0 + lg * 8 + j;
            g_conv1[((size_t)b * C1 + ch) * L1LEN + l] = fmaxf(acc[c][j], 0.f);
        }
    }
}

// ==================== conv2/3: FFMA2 + cp.async double-buffered ====================
#define CV_INSTRIDE 168
#define CV_INSZ (8 * CV_INSTRIDE * 4)       // 5376
#define CV_WSZ  (56 * 64 * 8)               // 28672
#define CV_BUFSZ (CV_INSZ + CV_WSZ)         // 34048
#define CV_SMEM  (2 * CV_BUFSZ)             // 68096

template <int CI, int CO, int LOUT, bool RELU, bool TRANS_OUT, int STAGE>
__global__ __launch_bounds__(256, 3) void conv_fast_kernel(const float* __restrict__ bias) {
    const float*  in = (STAGE == 2) ? g_conv1 : g_conv2;
    const float2* wp = (STAGE == 2) ? g_w2p : g_w3p;
    float*       out = (STAGE == 2) ? g_conv2 : g_feats;

    const int LIN = 2 * LOUT;
    const int NCH = CI / 8;
    extern __shared__ __align__(16) char dsm[];
    uint32_t sb = smem_u32(dsm);

    int tid = threadIdx.x;
    int lane = tid & 31, lg = tid >> 5;
    int l0  = blockIdx.x * 64;
    int cb  = blockIdx.y;
    int b   = blockIdx.z;

    const int gs = 2 * l0 - 16;

    auto stage_chunk = [&](int kc, int s) {
        uint32_t base = sb + s * CV_BUFSZ;
#pragma unroll
        for (int r = 0; r < 2; r++) {
            int i = tid + r * 256;
            if (i < 320) {
                int ci = i / 40, q = i % 40;
                int gf = gs + q * 4;
                int valid = (gf >= 0 && gf + 4 <= LIN) ? 16 : 0;
                const float* src = in + ((size_t)b * CI + kc * 8 + ci) * LIN + (gf < 0 ? 0 : gf);
                cp_async16z(base + ci * (CV_INSTRIDE * 4) + q * 16, src, valid);
            }
        }
        const char* wsrc = (const char*)(wp + ((size_t)cb * NCH + kc) * 3584);
        uint32_t wdst = base + CV_INSZ;
#pragma unroll
        for (int r = 0; r < 7; r++) {
            int i = tid + r * 256;
            cp_async16(wdst + i * 16, wsrc + i * 16);
        }
        CP_COMMIT();
    };

    uint64_t acc2[2][8];
#pragma unroll
    for (int cp = 0; cp < 2; cp++)
#pragma unroll
        for (int j = 0; j < 8; j++) acc2[cp][j] = 0ull;

    stage_chunk(0, 0);

    for (int kc = 0; kc < NCH; kc++) {
        CP_WAIT0();
        __syncthreads();
        if (kc + 1 < NCH) stage_chunk(kc + 1, (kc + 1) & 1);

        const float*  in_s = (const float*)(dsm + (kc & 1) * CV_BUFSZ);
        const float2* w_s  = (const float2*)(dsm + (kc & 1) * CV_BUFSZ + CV_INSZ);

#pragma unroll
        for (int ci = 0; ci < 8; ci++) {
            const float* inrow = in_s + ci * CV_INSTRIDE + 13 + 16 * lg;
            float xvf[21];
#pragma unroll
            for (int p = 0; p < 21; p++) xvf[p] = inrow[p];

#pragma unroll
            for (int t = 0; t < 7; t++) {
                const float2* wrow = w_s + (ci * 7 + t) * 64;
                float2 w0f = wrow[lane];
                float2 w1f = wrow[32 + lane];
                uint64_t w0, w1;
                memcpy(&w0, &w0f, 8);
                memcpy(&w1, &w1f, 8);
#pragma unroll
                for (int j = 0; j < 8; j++) {
                    uint64_t xd = pkdup(xvf[2 * j + t]);
                    fma2(acc2[0][j], w0, xd);
                    fma2(acc2[1][j], w1, xd);
                }
            }
        }
        __syncthreads();
    }

#pragma unroll
    for (int cp = 0; cp < 2; cp++) {
#pragma unroll
        for (int half = 0; half < 2; half++) {
            int c = cp * 2 + half;
            int co = cb * 128 + lane + 32 * c;
            float bv = bias[co];
#pragma unroll
            for (int j = 0; j < 8; j++) {
                float2 a = upk(acc2[cp][j]);
                float r = (half == 0 ? a.x : a.y) + bv;
                if (RELU) r = fmaxf(r, 0.f);
                int l = l0 + lg * 8 + j;
                if (TRANS_OUT) {
                    size_t idx = ((size_t)b * LOUT + l) * CO + co;
                    out[idx] = r;
                    g_fhi[idx] = __float2bfloat16_rn(r);
                } else {
                    out[((size_t)b * CO + co) * LOUT + l] = r;
                }
            }
        }
    }
}

// ==================== codebook prep ====================
__global__ void split_cb_kernel(const float* __restrict__ cb) {
    int i = blockIdx.x * blockDim.x + threadIdx.x;
    if (i >= KCB * VOCAB * HID) return;
    g_chi[i] = __float2bfloat16_rn(cb[i]);
}

__global__ void c2_kernel(const float* __restrict__ cb) {
    int row = blockIdx.x * 8 + (threadIdx.x >> 5);
    int lane = threadIdx.x & 31;
    const float* p = cb + (size_t)row * HID;
    float s = 0.f;
#pragma unroll 4
    for (int h = lane; h < HID; h += 32) {
        float v = p[h];
        s = fmaf(v, v, s);
    }
#pragma unroll
    for (int off = 16; off; off >>= 1)
        s += __shfl_xor_sync(0xffffffffu, s, off);
    if (lane == 0) g_c2[row] = s;
}

__global__ void f2_kernel() {
    int row = blockIdx.x * 8 + (threadIdx.x >> 5);
    int lane = threadIdx.x & 31;
    const float* p = g_feats + (size_t)row * HID;
    float s = 0.f;
#pragma unroll 4
    for (int h = lane; h < HID; h += 32) {
        float v = p[h];
        s = fmaf(v, v, s);
    }
#pragma unroll
    for (int off = 16; off; off >>= 1)
        s += __shfl_xor_sync(0xffffffffu, s, off);
    if (lane == 0) g_f2[row] = s;
}

__global__ void cbmax_kernel() {
    __shared__ float red[256];
    int k = blockIdx.x;
    float m = 0.f;
    for (int v = threadIdx.x; v < VOCAB; v += 256)
        m = fmaxf(m, g_c2[k * VOCAB + v]);
    red[threadIdx.x] = m;
    __syncthreads();
    for (int s = 128; s; s >>= 1) {
        if (threadIdx.x < s) red[threadIdx.x] = fmaxf(red[threadIdx.x], red[threadIdx.x + s]);
        __syncthreads();
    }
    if (threadIdx.x == 0) g_cbmax[k] = sqrtf(red[0]);
}

// ==================== stage 1: bf16 GEMM -> fp16 DIST dump (R12 structure) ====================
#define ST_A 0
#define ST_B 18432
#define ST_STRIDE 55296        // A(128x144) + B(256x144)
#define ST_C2 (2 * ST_STRIDE)  // 110592 .. +1024
#define ST_TOTAL (ST_C2 + 1024)

__global__ __launch_bounds__(256, 1) void gemm_hi_kernel() {
    extern __shared__ char smem[];
    uint32_t sbase = smem_u32(smem);
    float* c2_s = (float*)(smem + ST_C2);

    const int tid = threadIdx.x;
    const int wid = tid >> 5, lane = tid & 31;
    const int wm = wid >> 2, wn = wid & 3;
    const int g = lane >> 2, t = lane & 3;
    const int lt = blockIdx.x;
    const int vt = blockIdx.y;
    const int bk = blockIdx.z;
    const int b = bk >> 2, k = bk & 3;

    const __nv_bfloat16* A  = g_fhi + ((size_t)b * L3LEN + lt * 128) * HID;
    const __nv_bfloat16* Bm = g_chi + ((size_t)k * VOCAB + vt * 256) * HID;

    auto load_chunk = [&](int kc, int s) {
        uint32_t st = sbase + s * ST_STRIDE;
#pragma unroll
        for (int j = 0; j < 12; j++) {
            int idx = tid + j * 256;
            if (idx < 1024) {
                int r = idx >> 3, q = idx & 7;
                cp_async16(st + ST_A + r * 144 + q * 16,
                           A + (size_t)r * HID + kc * 64 + q * 8);
            } else {
                int i2 = idx - 1024;
                int r = i2 >> 3, q = i2 & 7;
                cp_async16(st + ST_B + r * 144 + q * 16,
                           Bm + (size_t)r * HID + kc * 64 + q * 8);
            }
        }
        CP_COMMIT();
    };

    int lrow = (lane & 7) + ((lane >> 3) & 1) * 8;
    int lcol = (lane >> 4) * 16;
    uint32_t a_ad[2][4], b_ad[2][4];
#pragma unroll
    for (int s = 0; s < 2; s++) {
#pragma unroll
        for (int mi = 0; mi < 4; mi++)
            a_ad[s][mi] = sbase + s * ST_STRIDE + ST_A +
                          (wm * 64 + mi * 16 + lrow) * 144 + lcol;
#pragma unroll
        for (int j = 0; j < 4; j++)
            b_ad[s][j] = sbase + s * ST_STRIDE + ST_B +
                         (wn * 64 + j * 16 + lrow) * 144 + lcol;
    }

    load_chunk(0, 0);
    if (tid < 256) c2_s[tid] = g_c2[k * VOCAB + vt * 256 + tid];

    float acc[4][8][4];
#pragma unroll
    for (int mi = 0; mi < 4; mi++)
#pragma unroll
        for (int ni = 0; ni < 8; ni++)
#pragma unroll
            for (int j = 0; j < 4; j++) acc[mi][ni][j] = 0.f;

    for (int kc = 0; kc < 8; kc++) {
        if (kc < 7) {
            load_chunk(kc + 1, (kc + 1) & 1);
            CP_WAIT1();
        } else {
            CP_WAIT0();
        }
        __syncthreads();
        int st = kc & 1;
#pragma unroll
        for (int ks = 0; ks < 4; ks++) {
            uint32_t af[4][4], bfv[4][4];
#pragma unroll
            for (int mi = 0; mi < 4; mi++) ldsm_x4(af[mi], a_ad[st][mi] + ks * 32);
#pragma unroll
            for (int j = 0; j < 4; j++)  ldsm_x4(bfv[j], b_ad[st][j] + ks * 32);
#pragma unroll
            for (int j = 0; j < 4; j++) {
#pragma unroll
                for (int mi = 0; mi < 4; mi++) {
                    mma_bf16(acc[mi][2 * j],     af[mi], &bfv[j][0], &bfv[j][2]);
                    mma_bf16(acc[mi][2 * j + 1], af[mi], &bfv[j][1], &bfv[j][3]);
                }
            }
        }
        __syncthreads();
    }

    // epilogue: dist = c2 - 2*cross, fp16 dump
#pragma unroll
    for (int mi = 0; mi < 4; mi++) {
        int row = lt * 128 + wm * 64 + mi * 16 + g;
        size_t code = (size_t)bk * L3LEN + row;
        __half* out0 = g_dist + code * VOCAB;
        __half* out1 = g_dist + (code + 8) * VOCAB;
#pragma unroll
        for (int ni = 0; ni < 8; ni++) {
            int cl = wn * 64 + ni * 8 + 2 * t;
            int col = vt * 256 + cl;
            float d00 = c2_s[cl]     - 2.f * acc[mi][ni][0];
            float d01 = c2_s[cl + 1] - 2.f * acc[mi][ni][1];
            float d10 = c2_s[cl]     - 2.f * acc[mi][ni][2];
            float d11 = c2_s[cl + 1] - 2.f * acc[mi][ni][3];
            *(__half2*)(out0 + col) = __floats2half2_rn(d00, d01);
            *(__half2*)(out1 + col) = __floats2half2_rn(d10, d11);
        }
    }
}

// ==================== stage 2: warp-per-token select + bounded exact rescore ====================
__global__ __launch_bounds__(256) void select_kernel(const float* __restrict__ cb) {
    int lane = threadIdx.x & 31;
    int wid = threadIdx.x >> 5;
    int code = blockIdx.x * 8 + wid;           // one warp per token
    int l = code & (L3LEN - 1);
    int bk = code >> 12;
    int k = bk & (KCB - 1);
    int b = bk >> 2;

    const int4* drow = (const int4*)(g_dist + (size_t)code * VOCAB);

    // sweep: 8 iters x int4 (8 halves) per lane
    float minv = CUDART_INF_F, min2 = CUDART_INF_F;
    int mini = 0;
#pragma unroll
    for (int i = 0; i < 8; i++) {
        int4 pk = drow[i * 32 + lane];
        const __half2* h2 = (const __half2*)&pk;
        int v0 = i * 256 + lane * 8;
#pragma unroll
        for (int q = 0; q < 4; q++) {
            float d0 = __low2float(h2[q]);
            float d1 = __high2float(h2[q]);
            upd_min(minv, min2, mini, d0, v0 + 2 * q);
            upd_min(minv, min2, mini, d1, v0 + 2 * q + 1);
        }
    }
#pragma unroll
    for (int off = 16; off; off >>= 1) {
        float om  = __shfl_xor_sync(0xffffffffu, minv, off);
        float om2 = __shfl_xor_sync(0xffffffffu, min2, off);
        int   oi  = __shfl_xor_sync(0xffffffffu, mini, off);
        merge_min(minv, min2, mini, om, om2, oi);
    }

    float TH = 0.009f * sqrtf(g_f2[b * L3LEN + l]) * g_cbmax[k] + 1.0f;
    if (min2 - minv > TH) {
        if (lane == 0) g_tokens[code] = mini;
        return;
    }

    // bounded exact rescore of candidates within TH of min
    const float* f = g_feats + ((size_t)b * L3LEN + l) * HID;
    float fr[16];
#pragma unroll
    for (int j = 0; j < 16; j++) fr[j] = f[j * 32 + lane];

    float thr = minv + TH;
    float bestd = CUDART_INF_F;
    int besti = VOCAB;
    for (int i = 0; i < 8; i++) {
        int4 pk = drow[i * 32 + lane];
        const __half2* h2 = (const __half2*)&pk;
#pragma unroll
        for (int q = 0; q < 4; q++) {
            float d0 = __low2float(h2[q]);
            float d1 = __high2float(h2[q]);
            unsigned m0 = __ballot_sync(0xffffffffu, d0 <= thr);
            unsigned m1 = __ballot_sync(0xffffffffu, d1 <= thr);
            while (m0 | m1) {
                int s0 = m0 ? (__ffs(m0) - 1) : 33;
                int s1 = m1 ? (__ffs(m1) - 1) : 33;
                int vc;
                if (s0 <= s1) { vc = i * 256 + s0 * 8 + 2 * q;     m0 &= m0 - 1; }
                else          { vc = i * 256 + s1 * 8 + 2 * q + 1; m1 &= m1 - 1; }
                const float* c = cb + ((size_t)k * VOCAB + vc) * HID;
                float dot = 0.f;
#pragma unroll
                for (int j = 0; j < 16; j++)
                    dot = fmaf(fr[j], c[j * 32 + lane], dot);
#pragma unroll
                for (int off = 16; off; off >>= 1)
                    dot += __shfl_xor_sync(0xffffffffu, dot, off);
                float de = __ldg(g_c2 + k * VOCAB + vc) - 2.f * dot;
                if (de < bestd || (de == bestd && vc < besti)) { bestd = de; besti = vc; }
            }
        }
    }
    if (lane == 0) g_tokens[code] = besti;
}

// ==================== outputs ====================
__global__ void emb_kernel(const float* __restrict__ embedding, float* __restrict__ out) {
    int bl = blockIdx.x;
    int b = bl >> 12;
    int l = bl & (L3LEN - 1);
    int t0 = g_tokens[((size_t)b * KCB + 0) * L3LEN + l];
    int t1 = g_tokens[((size_t)b * KCB + 1) * L3LEN + l];
    int t2 = g_tokens[((size_t)b * KCB + 2) * L3LEN + l];
    int t3 = g_tokens[((size_t)b * KCB + 3) * L3LEN + l];
    const float4* e0 = (const float4*)(embedding + (size_t)t0 * HID);
    const float4* e1 = (const float4*)(embedding + (size_t)t1 * HID);
    const float4* e2 = (const float4*)(embedding + (size_t)t2 * HID);
    const float4* e3 = (const float4*)(embedding + (size_t)t3 * HID);
    int h = threadIdx.x;
    float4 v0 = e0[h], v1 = e1[h], v2 = e2[h], v3 = e3[h];
    float4 rr;
    rr.x = 0.25f * (v0.x + v1.x + v2.x + v3.x);
    rr.y = 0.25f * (v0.y + v1.y + v2.y + v3.y);
    rr.z = 0.25f * (v0.z + v1.z + v2.z + v3.z);
    rr.w = 0.25f * (v0.w + v1.w + v2.w + v3.w);
    ((float4*)(out + ((size_t)b * L3LEN + l) * HID))[h] = rr;
}

__global__ void tok2f_kernel(float* __restrict__ out) {
    int i = blockIdx.x * blockDim.x + threadIdx.x;
    if (i < NTOK) out[i] = (float)g_tokens[i];
}

// ==================== launch ====================
extern "C" void kernel_launch(void* const* d_in, const int* in_sizes, int n_in,
                              void* d_out, int out_size) {
    const float* audio = 0; const float* w1 = 0; const float* b1 = 0;
    const float* w2 = 0; const float* b2 = 0; const float* w3 = 0; const float* b3 = 0;
    const float* codebook = 0; const float* embedding = 0;
    for (int i = 0; i < n_in; i++) {
        const float* p = (const float*)d_in[i];
        switch (in_sizes[i]) {
            case BATCH * SLEN:      audio = p; break;
            case C1 * 1 * 7:        w1 = p; break;
            case C1:                b1 = p; break;
            case C2 * C1 * 7:       w2 = p; break;
            case C2:                b2 = p; break;
            case HID * C2 * 7:      w3 = p; break;
            case HID:               b3 = p; break;
            case KCB * VOCAB * HID: codebook = p; break;
            case VOCAB * HID:       embedding = p; break;
            default: break;
        }
    }

    cudaFuncSetAttribute(gemm_hi_kernel,
                         cudaFuncAttributeMaxDynamicSharedMemorySize, ST_TOTAL);
    cudaFuncSetAttribute(conv_fast_kernel<C1, C2, L2LEN, true, false, 2>,
                         cudaFuncAttributeMaxDynamicSharedMemorySize, CV_SMEM);
    cudaFuncSetAttribute(conv_fast_kernel<C2, HID, L3LEN, false, true, 3>,
                         cudaFuncAttributeMaxDynamicSharedMemorySize, CV_SMEM);

    // order keeps the 4th launch (ncu capture slot) = conv_fast<stage2>
    {
        dim3 grid(L1LEN / 64, BATCH);
        conv1_fast_kernel<<<grid, 256>>>(audio, w1, b1);
    }
    wpack_kernel<C1, C2, 2><<<((C2 / 128) * (C1 / 8) * 3584 + 255) / 256, 256>>>(w2);
    wpack_kernel<C2, HID, 3><<<((HID / 128) * (C2 / 8) * 3584 + 255) / 256, 256>>>(w3);
    {
        dim3 grid(L2LEN / 64, C2 / 128, BATCH);
        conv_fast_kernel<C1, C2, L2LEN, true, false, 2><<<grid, 256, CV_SMEM>>>(b2);
    }
    {
        dim3 grid(L3LEN / 64, HID / 128, BATCH);
        conv_fast_kernel<C2, HID, L3LEN, false, true, 3><<<grid, 256, CV_SMEM>>>(b3);
    }
    split_cb_kernel<<<(KCB * VOCAB * HID) / 256, 256>>>(codebook);
    c2_kernel<<<(KCB * VOCAB) / 8, 256>>>(codebook);
    f2_kernel<<<(BATCH * L3LEN) / 8, 256>>>();
    cbmax_kernel<<<KCB, 256>>>();

    {
        dim3 grid(L3LEN / 128, VOCAB / 256, KCB * BATCH);
        gemm_hi_kernel<<<grid, 256, ST_TOTAL>>>();
    }
    select_kernel<<<NTOK / 8, 256>>>(codebook);

    const int TOK = NTOK;
    const int EMB = BATCH * L3LEN * HID;
    float* out = (float*)d_out;
    if (out_size >= TOK + EMB) {
        tok2f_kernel<<<(TOK + 255) / 256, 256>>>(out);
        emb_kernel<<<BATCH * L3LEN, 128>>>(embedding, out + TOK);
    } else if (out_size >= EMB) {
        emb_kernel<<<BATCH * L3LEN, 128>>>(embedding, out);
    } else {
        tok2f_kernel<<<(TOK + 255) / 256, 256>>>(out);
    }
}

// round 17
// speedup vs baseline: 47.4273x; 1.0237x over previous
#include <cuda_runtime.h>
#include <cuda_bf16.h>
#include <cuda_fp16.h>
#include <math_constants.h>
#include <cstdint>
#include <cstring>

// Problem constants
#define BATCH 4
#define SLEN  32768
#define C1    128
#define C2    256
#define HID   512
#define L1LEN 16384
#define L2LEN 8192
#define L3LEN 4096
#define VOCAB 2048
#define KCB   4
#define NTOK  (BATCH * KCB * L3LEN)      // 65536

// ------------------- device scratch (device-code references ONLY) -------------------
__device__ __align__(16) float g_conv1[BATCH * C1 * L1LEN];
__device__ __align__(16) float g_conv2[BATCH * C2 * L2LEN];
__device__ __align__(16) float g_feats[BATCH * L3LEN * HID];       // fp32 exact
__device__ __align__(16) float2 g_w2p[(C2 / 128) * (C1 / 8) * 56 * 64];
__device__ __align__(16) float2 g_w3p[(HID / 128) * (C2 / 8) * 56 * 64];
__device__ __align__(16) __nv_bfloat16 g_fhi[BATCH * L3LEN * HID];
__device__ __align__(16) __nv_bfloat16 g_chi[KCB * VOCAB * HID];
__device__ __align__(16) __half g_dist[(size_t)NTOK * VOCAB];      // fp16 approx dists
__device__ float g_c2[KCB * VOCAB];
__device__ float g_f2[BATCH * L3LEN];
__device__ float g_cbmax[KCB];
__device__ int   g_tokens[NTOK];

// ==================== helpers ====================
__device__ __forceinline__ uint64_t pkdup(float v) {
    uint64_t r; asm("mov.b64 %0, {%1, %1};" : "=l"(r) : "f"(v)); return r;
}
__device__ __forceinline__ void fma2(uint64_t& c, uint64_t a, uint64_t b) {
    asm("fma.rn.f32x2 %0, %1, %2, %0;" : "+l"(c) : "l"(a), "l"(b));
}
__device__ __forceinline__ float2 upk(uint64_t v) {
    float2 f; asm("mov.b64 {%0, %1}, %2;" : "=f"(f.x), "=f"(f.y) : "l"(v)); return f;
}
__device__ __forceinline__ uint32_t smem_u32(const void* p) {
    uint32_t a;
    asm("{ .reg .u64 t; cvta.to.shared.u64 t, %1; cvt.u32.u64 %0, t; }" : "=r"(a) : "l"(p));
    return a;
}
__device__ __forceinline__ void cp_async16(uint32_t s, const void* g) {
    asm volatile("cp.async.cg.shared.global [%0], [%1], 16;" :: "r"(s), "l"(g) : "memory");
}
__device__ __forceinline__ void cp_async16z(uint32_t s, const void* g, int n) {
    asm volatile("cp.async.cg.shared.global [%0], [%1], 16, %2;" :: "r"(s), "l"(g), "r"(n) : "memory");
}
#define CP_COMMIT() asm volatile("cp.async.commit_group;" ::: "memory")
#define CP_WAIT0()  asm volatile("cp.async.wait_group 0;" ::: "memory")
#define CP_WAIT1()  asm volatile("cp.async.wait_group 1;" ::: "memory")

__device__ __forceinline__ void mma_bf16(float* c, const uint32_t* a, const uint32_t* b0, const uint32_t* b1) {
    asm volatile(
        "mma.sync.aligned.m16n8k16.row.col.f32.bf16.bf16.f32 "
        "{%0,%1,%2,%3}, {%4,%5,%6,%7}, {%8,%9}, {%0,%1,%2,%3};"
        : "+f"(c[0]), "+f"(c[1]), "+f"(c[2]), "+f"(c[3])
        : "r"(a[0]), "r"(a[1]), "r"(a[2]), "r"(a[3]), "r"(*b0), "r"(*b1));
}
__device__ __forceinline__ void ldsm_x4(uint32_t* r, uint32_t addr) {
    asm volatile("ldmatrix.sync.aligned.m8n8.x4.shared.b16 {%0,%1,%2,%3}, [%4];"
                 : "=r"(r[0]), "=r"(r[1]), "=r"(r[2]), "=r"(r[3]) : "r"(addr));
}
__device__ __forceinline__ void upd_min(float& m, float& m2, int& idx, float d, int v) {
    if (d < m)       { m2 = m; m = d; idx = v; }
    else if (d < m2) { m2 = d; }
}
__device__ __forceinline__ void merge_min(float& m, float& m2, int& idx,
                                          float om, float om2, int oidx) {
    if (om < m || (om == m && oidx < idx)) { m2 = fminf(m, om2); m = om; idx = oidx; }
    else                                   { m2 = fminf(m2, om); }
}

// ==================== merged weight pack (w2 + w3 in one launch) ====================
#define W2P_TOTAL ((C2 / 128) * (C1 / 8) * 56 * 64)     // 114688
#define W3P_TOTAL ((HID / 128) * (C2 / 8) * 56 * 64)    // 458752
__global__ void wpack_all_kernel(const float* __restrict__ w2, const float* __restrict__ w3) {
    int gi = blockIdx.x * 256 + threadIdx.x;
    if (gi < W2P_TOTAL) {
        const int CI = C1, CO = C2;
        int i = gi;
        int p = i & 63;
        int row = (i >> 6) % 56;
        int chunk = ((i >> 6) / 56) % (CI / 8);
        int cb = (i >> 6) / 56 / (CI / 8);
        int ci = chunk * 8 + row / 7;
        int t = row % 7;
        int c_lo = (p < 32) ? p : p + 32;
        int co_lo = cb * 128 + c_lo;
        g_w2p[i] = make_float2(w2[((size_t)co_lo * CI + ci) * 7 + t],
                               w2[((size_t)(co_lo + 32) * CI + ci) * 7 + t]);
    } else if (gi < W2P_TOTAL + W3P_TOTAL) {
        const int CI = C2, CO = HID;
        int i = gi - W2P_TOTAL;
        int p = i & 63;
        int row = (i >> 6) % 56;
        int chunk = ((i >> 6) / 56) % (CI / 8);
        int cb = (i >> 6) / 56 / (CI / 8);
        int ci = chunk * 8 + row / 7;
        int t = row % 7;
        int c_lo = (p < 32) ? p : p + 32;
        int co_lo = cb * 128 + c_lo;
        g_w3p[i] = make_float2(w3[((size_t)co_lo * CI + ci) * 7 + t],
                               w3[((size_t)(co_lo + 32) * CI + ci) * 7 + t]);
    }
}

// ==================== conv1 ====================
__global__ __launch_bounds__(256) void conv1_fast_kernel(const float* __restrict__ x,
                                                         const float* __restrict__ w,
                                                         const float* __restrict__ bias) {
    __shared__ float a_s[136];
    int tid = threadIdx.x;
    int lane = tid & 31, lg = tid >> 5;
    int l0 = blockIdx.x * 64;
    int b = blockIdx.y;

    for (int p = tid; p < 133; p += 256) {
        int pg = 2 * l0 - 3 + p;
        a_s[p] = (pg >= 0 && pg < SLEN) ? x[(size_t)b * SLEN + pg] : 0.f;
    }
    __syncthreads();

    float wr[4][7], bv[4];
#pragma unroll
    for (int c = 0; c < 4; c++) {
        int ch = lane + 32 * c;
        bv[c] = bias[ch];
#pragma unroll
        for (int t = 0; t < 7; t++) wr[c][t] = w[ch * 7 + t];
    }

    float xv[21];
#pragma unroll
    for (int p = 0; p < 21; p++) xv[p] = a_s[16 * lg + p];

    float acc[4][8];
#pragma unroll
    for (int c = 0; c < 4; c++)
#pragma unroll
        for (int j = 0; j < 8; j++) acc[c][j] = bv[c];
#pragma unroll
    for (int t = 0; t < 7; t++) {
#pragma unroll
        for (int j = 0; j < 8; j++) {
            float xx = xv[2 * j + t];
#pragma unroll
            for (int c = 0; c < 4; c++)
                acc[c][j] = fmaf(wr[c][t], xx, acc[c][j]);
        }
    }
#pragma unroll
    for (int c = 0; c < 4; c++) {
        int ch = lane + 32 * c;
#pragma unroll
        for (int j = 0; j < 8; j++) {
            int l = l0 + lg * 8 + j;
            g_conv1[((size_t)b * C1 + ch) * L1LEN + l] = fmaxf(acc[c][j], 0.f);
        }
    }
}

// ==================== conv2/3: FFMA2 + cp.async double-buffered ====================
#define CV_INSTRIDE 168
#define CV_INSZ (8 * CV_INSTRIDE * 4)       // 5376
#define CV_WSZ  (56 * 64 * 8)               // 28672
#define CV_BUFSZ (CV_INSZ + CV_WSZ)         // 34048
#define CV_SMEM  (2 * CV_BUFSZ)             // 68096

template <int CI, int CO, int LOUT, bool RELU, bool TRANS_OUT, int STAGE>
__global__ __launch_bounds__(256, 3) void conv_fast_kernel(const float* __restrict__ bias) {
    const float*  in = (STAGE == 2) ? g_conv1 : g_conv2;
    const float2* wp = (STAGE == 2) ? g_w2p : g_w3p;
    float*       out = (STAGE == 2) ? g_conv2 : g_feats;

    const int LIN = 2 * LOUT;
    const int NCH = CI / 8;
    extern __shared__ __align__(16) char dsm[];
    uint32_t sb = smem_u32(dsm);

    int tid = threadIdx.x;
    int lane = tid & 31, lg = tid >> 5;
    int l0  = blockIdx.x * 64;
    int cb  = blockIdx.y;
    int b   = blockIdx.z;

    const int gs = 2 * l0 - 16;

    auto stage_chunk = [&](int kc, int s) {
        uint32_t base = sb + s * CV_BUFSZ;
#pragma unroll
        for (int r = 0; r < 2; r++) {
            int i = tid + r * 256;
            if (i < 320) {
                int ci = i / 40, q = i % 40;
                int gf = gs + q * 4;
                int valid = (gf >= 0 && gf + 4 <= LIN) ? 16 : 0;
                const float* src = in + ((size_t)b * CI + kc * 8 + ci) * LIN + (gf < 0 ? 0 : gf);
                cp_async16z(base + ci * (CV_INSTRIDE * 4) + q * 16, src, valid);
            }
        }
        const char* wsrc = (const char*)(wp + ((size_t)cb * NCH + kc) * 3584);
        uint32_t wdst = base + CV_INSZ;
#pragma unroll
        for (int r = 0; r < 7; r++) {
            int i = tid + r * 256;
            cp_async16(wdst + i * 16, wsrc + i * 16);
        }
        CP_COMMIT();
    };

    uint64_t acc2[2][8];
#pragma unroll
    for (int cp = 0; cp < 2; cp++)
#pragma unroll
        for (int j = 0; j < 8; j++) acc2[cp][j] = 0ull;

    stage_chunk(0, 0);

    for (int kc = 0; kc < NCH; kc++) {
        CP_WAIT0();
        __syncthreads();           // orders cp data visibility AND buffer reuse
        if (kc + 1 < NCH) stage_chunk(kc + 1, (kc + 1) & 1);

        const float*  in_s = (const float*)(dsm + (kc & 1) * CV_BUFSZ);
        const float2* w_s  = (const float2*)(dsm + (kc & 1) * CV_BUFSZ + CV_INSZ);

#pragma unroll
        for (int ci = 0; ci < 8; ci++) {
            const float* inrow = in_s + ci * CV_INSTRIDE + 13 + 16 * lg;
            float xvf[21];
#pragma unroll
            for (int p = 0; p < 21; p++) xvf[p] = inrow[p];

#pragma unroll
            for (int t = 0; t < 7; t++) {
                const float2* wrow = w_s + (ci * 7 + t) * 64;
                float2 w0f = wrow[lane];
                float2 w1f = wrow[32 + lane];
                uint64_t w0, w1;
                memcpy(&w0, &w0f, 8);
                memcpy(&w1, &w1f, 8);
#pragma unroll
                for (int j = 0; j < 8; j++) {
                    uint64_t xd = pkdup(xvf[2 * j + t]);
                    fma2(acc2[0][j], w0, xd);
                    fma2(acc2[1][j], w1, xd);
                }
            }
        }
        // no trailing sync: next iteration's top sync provides the ordering
    }

#pragma unroll
    for (int cp = 0; cp < 2; cp++) {
#pragma unroll
        for (int half = 0; half < 2; half++) {
            int c = cp * 2 + half;
            int co = cb * 128 + lane + 32 * c;
            float bv = bias[co];
#pragma unroll
            for (int j = 0; j < 8; j++) {
                float2 a = upk(acc2[cp][j]);
                float r = (half == 0 ? a.x : a.y) + bv;
                if (RELU) r = fmaxf(r, 0.f);
                int l = l0 + lg * 8 + j;
                if (TRANS_OUT) {
                    size_t idx = ((size_t)b * LOUT + l) * CO + co;
                    out[idx] = r;
                    g_fhi[idx] = __float2bfloat16_rn(r);
                } else {
                    out[((size_t)b * CO + co) * LOUT + l] = r;
                }
            }
        }
    }
}

// ==================== codebook prep ====================
__global__ void split_cb_kernel(const float* __restrict__ cb) {
    int i = blockIdx.x * blockDim.x + threadIdx.x;
    if (i >= KCB * VOCAB * HID) return;
    g_chi[i] = __float2bfloat16_rn(cb[i]);
}

__global__ void c2_kernel(const float* __restrict__ cb) {
    int row = blockIdx.x * 8 + (threadIdx.x >> 5);
    int lane = threadIdx.x & 31;
    const float* p = cb + (size_t)row * HID;
    float s = 0.f;
#pragma unroll 4
    for (int h = lane; h < HID; h += 32) {
        float v = p[h];
        s = fmaf(v, v, s);
    }
#pragma unroll
    for (int off = 16; off; off >>= 1)
        s += __shfl_xor_sync(0xffffffffu, s, off);
    if (lane == 0) g_c2[row] = s;
}

__global__ void f2_kernel() {
    int row = blockIdx.x * 8 + (threadIdx.x >> 5);
    int lane = threadIdx.x & 31;
    const float* p = g_feats + (size_t)row * HID;
    float s = 0.f;
#pragma unroll 4
    for (int h = lane; h < HID; h += 32) {
        float v = p[h];
        s = fmaf(v, v, s);
    }
#pragma unroll
    for (int off = 16; off; off >>= 1)
        s += __shfl_xor_sync(0xffffffffu, s, off);
    if (lane == 0) g_f2[row] = s;
}

__global__ void cbmax_kernel() {
    __shared__ float red[256];
    int k = blockIdx.x;
    float m = 0.f;
    for (int v = threadIdx.x; v < VOCAB; v += 256)
        m = fmaxf(m, g_c2[k * VOCAB + v]);
    red[threadIdx.x] = m;
    __syncthreads();
    for (int s = 128; s; s >>= 1) {
        if (threadIdx.x < s) red[threadIdx.x] = fmaxf(red[threadIdx.x], red[threadIdx.x + s]);
        __syncthreads();
    }
    if (threadIdx.x == 0) g_cbmax[k] = sqrtf(red[0]);
}

// ==================== stage 1: bf16 GEMM 128x128 tile, 2 blocks/SM -> fp16 dist ====================
#define ST_A 0
#define ST_B 18432
#define ST_STRIDE 36864        // A(128x144) + B(128x144)
#define ST_C2 (2 * ST_STRIDE)  // 73728 .. +512
#define ST_TOTAL (ST_C2 + 512)

__global__ __launch_bounds__(256, 2) void gemm_hi_kernel() {
    extern __shared__ char smem[];
    uint32_t sbase = smem_u32(smem);
    float* c2_s = (float*)(smem + ST_C2);

    const int tid = threadIdx.x;
    const int wid = tid >> 5, lane = tid & 31;
    const int wm = wid >> 2, wn = wid & 3;
    const int g = lane >> 2, t = lane & 3;
    const int lt = blockIdx.x;
    const int vt = blockIdx.y;          // 16 x 128-col slices
    const int bk = blockIdx.z;
    const int b = bk >> 2, k = bk & 3;

    const __nv_bfloat16* A  = g_fhi + ((size_t)b * L3LEN + lt * 128) * HID;
    const __nv_bfloat16* Bm = g_chi + ((size_t)k * VOCAB + vt * 128) * HID;

    auto load_chunk = [&](int kc, int s) {
        uint32_t st = sbase + s * ST_STRIDE;
#pragma unroll
        for (int j = 0; j < 8; j++) {
            int idx = tid + j * 256;    // 0..2047
            int r = (idx >> 3) & 127, q = idx & 7;
            if (idx < 1024) {
                cp_async16(st + ST_A + r * 144 + q * 16,
                           A + (size_t)r * HID + kc * 64 + q * 8);
            } else {
                cp_async16(st + ST_B + r * 144 + q * 16,
                           Bm + (size_t)r * HID + kc * 64 + q * 8);
            }
        }
        CP_COMMIT();
    };

    int lrow = (lane & 7) + ((lane >> 3) & 1) * 8;
    int lcol = (lane >> 4) * 16;
    uint32_t a_ad[2][4], b_ad[2][2];
#pragma unroll
    for (int s = 0; s < 2; s++) {
#pragma unroll
        for (int mi = 0; mi < 4; mi++)
            a_ad[s][mi] = sbase + s * ST_STRIDE + ST_A +
                          (wm * 64 + mi * 16 + lrow) * 144 + lcol;
#pragma unroll
        for (int j = 0; j < 2; j++)
            b_ad[s][j] = sbase + s * ST_STRIDE + ST_B +
                         (wn * 32 + j * 16 + lrow) * 144 + lcol;
    }

    load_chunk(0, 0);
    if (tid < 128) c2_s[tid] = g_c2[k * VOCAB + vt * 128 + tid];

    float acc[4][4][4];
#pragma unroll
    for (int mi = 0; mi < 4; mi++)
#pragma unroll
        for (int ni = 0; ni < 4; ni++)
#pragma unroll
            for (int j = 0; j < 4; j++) acc[mi][ni][j] = 0.f;

    for (int kc = 0; kc < 8; kc++) {
        if (kc < 7) {
            load_chunk(kc + 1, (kc + 1) & 1);
            CP_WAIT1();
        } else {
            CP_WAIT0();
        }
        __syncthreads();
        int st = kc & 1;
#pragma unroll
        for (int ks = 0; ks < 4; ks++) {
            uint32_t af[4][4], bfv[2][4];
#pragma unroll
            for (int mi = 0; mi < 4; mi++) ldsm_x4(af[mi], a_ad[st][mi] + ks * 32);
#pragma unroll
            for (int j = 0; j < 2; j++)  ldsm_x4(bfv[j], b_ad[st][j] + ks * 32);
#pragma unroll
            for (int j = 0; j < 2; j++) {
#pragma unroll
                for (int mi = 0; mi < 4; mi++) {
                    mma_bf16(acc[mi][2 * j],     af[mi], &bfv[j][0], &bfv[j][2]);
                    mma_bf16(acc[mi][2 * j + 1], af[mi], &bfv[j][1], &bfv[j][3]);
                }
            }
        }
        __syncthreads();
    }

    // epilogue: dist = c2 - 2*cross, fp16 dump
#pragma unroll
    for (int mi = 0; mi < 4; mi++) {
        int row = lt * 128 + wm * 64 + mi * 16 + g;
        size_t code = (size_t)bk * L3LEN + row;
        __half* out0 = g_dist + code * VOCAB;
        __half* out1 = g_dist + (code + 8) * VOCAB;
#pragma unroll
        for (int ni = 0; ni < 4; ni++) {
            int cl = wn * 32 + ni * 8 + 2 * t;
            int col = vt * 128 + cl;
            float d00 = c2_s[cl]     - 2.f * acc[mi][ni][0];
            float d01 = c2_s[cl + 1] - 2.f * acc[mi][ni][1];
            float d10 = c2_s[cl]     - 2.f * acc[mi][ni][2];
            float d11 = c2_s[cl + 1] - 2.f * acc[mi][ni][3];
            *(__half2*)(out0 + col) = __floats2half2_rn(d00, d01);
            *(__half2*)(out1 + col) = __floats2half2_rn(d10, d11);
        }
    }
}

// ==================== stage 2: warp-per-token select + bounded exact rescore ====================
__global__ __launch_bounds__(256) void select_kernel(const float* __restrict__ cb) {
    int lane = threadIdx.x & 31;
    int wid = threadIdx.x >> 5;
    int code = blockIdx.x * 8 + wid;           // one warp per token
    int l = code & (L3LEN - 1);
    int bk = code >> 12;
    int k = bk & (KCB - 1);
    int b = bk >> 2;

    const int4* drow = (const int4*)(g_dist + (size_t)code * VOCAB);

    float minv = CUDART_INF_F, min2 = CUDART_INF_F;
    int mini = 0;
#pragma unroll
    for (int i = 0; i < 8; i++) {
        int4 pk = drow[i * 32 + lane];
        const __half2* h2 = (const __half2*)&pk;
        int v0 = i * 256 + lane * 8;
#pragma unroll
        for (int q = 0; q < 4; q++) {
            float d0 = __low2float(h2[q]);
            float d1 = __high2float(h2[q]);
            upd_min(minv, min2, mini, d0, v0 + 2 * q);
            upd_min(minv, min2, mini, d1, v0 + 2 * q + 1);
        }
    }
#pragma unroll
    for (int off = 16; off; off >>= 1) {
        float om  = __shfl_xor_sync(0xffffffffu, minv, off);
        float om2 = __shfl_xor_sync(0xffffffffu, min2, off);
        int   oi  = __shfl_xor_sync(0xffffffffu, mini, off);
        merge_min(minv, min2, mini, om, om2, oi);
    }

    float TH = 0.009f * sqrtf(g_f2[b * L3LEN + l]) * g_cbmax[k] + 1.0f;
    if (min2 - minv > TH) {
        if (lane == 0) g_tokens[code] = mini;
        return;
    }

    const float* f = g_feats + ((size_t)b * L3LEN + l) * HID;
    float fr[16];
#pragma unroll
    for (int j = 0; j < 16; j++) fr[j] = f[j * 32 + lane];

    float thr = minv + TH;
    float bestd = CUDART_INF_F;
    int besti = VOCAB;
    for (int i = 0; i < 8; i++) {
        int4 pk = drow[i * 32 + lane];
        const __half2* h2 = (const __half2*)&pk;
#pragma unroll
        for (int q = 0; q < 4; q++) {
            float d0 = __low2float(h2[q]);
            float d1 = __high2float(h2[q]);
            unsigned m0 = __ballot_sync(0xffffffffu, d0 <= thr);
            unsigned m1 = __ballot_sync(0xffffffffu, d1 <= thr);
            while (m0 | m1) {
                int s0 = m0 ? (__ffs(m0) - 1) : 33;
                int s1 = m1 ? (__ffs(m1) - 1) : 33;
                int vc;
                if (s0 <= s1) { vc = i * 256 + s0 * 8 + 2 * q;     m0 &= m0 - 1; }
                else          { vc = i * 256 + s1 * 8 + 2 * q + 1; m1 &= m1 - 1; }
                const float* c = cb + ((size_t)k * VOCAB + vc) * HID;
                float dot = 0.f;
#pragma unroll
                for (int j = 0; j < 16; j++)
                    dot = fmaf(fr[j], c[j * 32 + lane], dot);
#pragma unroll
                for (int off = 16; off; off >>= 1)
                    dot += __shfl_xor_sync(0xffffffffu, dot, off);
                float de = __ldg(g_c2 + k * VOCAB + vc) - 2.f * dot;
                if (de < bestd || (de == bestd && vc < besti)) { bestd = de; besti = vc; }
            }
        }
    }
    if (lane == 0) g_tokens[code] = besti;
}

// ==================== outputs ====================
__global__ void emb_kernel(const float* __restrict__ embedding, float* __restrict__ out) {
    int bl = blockIdx.x;
    int b = bl >> 12;
    int l = bl & (L3LEN - 1);
    int t0 = g_tokens[((size_t)b * KCB + 0) * L3LEN + l];
    int t1 = g_tokens[((size_t)b * KCB + 1) * L3LEN + l];
    int t2 = g_tokens[((size_t)b * KCB + 2) * L3LEN + l];
    int t3 = g_tokens[((size_t)b * KCB + 3) * L3LEN + l];
    const float4* e0 = (const float4*)(embedding + (size_t)t0 * HID);
    const float4* e1 = (const float4*)(embedding + (size_t)t1 * HID);
    const float4* e2 = (const float4*)(embedding + (size_t)t2 * HID);
    const float4* e3 = (const float4*)(embedding + (size_t)t3 * HID);
    int h = threadIdx.x;
    float4 v0 = e0[h], v1 = e1[h], v2 = e2[h], v3 = e3[h];
    float4 rr;
    rr.x = 0.25f * (v0.x + v1.x + v2.x + v3.x);
    rr.y = 0.25f * (v0.y + v1.y + v2.y + v3.y);
    rr.z = 0.25f * (v0.z + v1.z + v2.z + v3.z);
    rr.w = 0.25f * (v0.w + v1.w + v2.w + v3.w);
    ((float4*)(out + ((size_t)b * L3LEN + l) * HID))[h] = rr;
}

__global__ void tok2f_kernel(float* __restrict__ out) {
    int i = blockIdx.x * blockDim.x + threadIdx.x;
    if (i < NTOK) out[i] = (float)g_tokens[i];
}

// ==================== launch ====================
extern "C" void kernel_launch(void* const* d_in, const int* in_sizes, int n_in,
                              void* d_out, int out_size) {
    const float* audio = 0; const float* w1 = 0; const float* b1 = 0;
    const float* w2 = 0; const float* b2 = 0; const float* w3 = 0; const float* b3 = 0;
    const float* codebook = 0; const float* embedding = 0;
    for (int i = 0; i < n_in; i++) {
        const float* p = (const float*)d_in[i];
        switch (in_sizes[i]) {
            case BATCH * SLEN:      audio = p; break;
            case C1 * 1 * 7:        w1 = p; break;
            case C1:                b1 = p; break;
            case C2 * C1 * 7:       w2 = p; break;
            case C2:                b2 = p; break;
            case HID * C2 * 7:      w3 = p; break;
            case HID:               b3 = p; break;
            case KCB * VOCAB * HID: codebook = p; break;
            case VOCAB * HID:       embedding = p; break;
            default: break;
        }
    }

    cudaFuncSetAttribute(gemm_hi_kernel,
                         cudaFuncAttributeMaxDynamicSharedMemorySize, ST_TOTAL);
    cudaFuncSetAttribute(conv_fast_kernel<C1, C2, L2LEN, true, false, 2>,
                         cudaFuncAttributeMaxDynamicSharedMemorySize, CV_SMEM);
    cudaFuncSetAttribute(conv_fast_kernel<C2, HID, L3LEN, false, true, 3>,
                         cudaFuncAttributeMaxDynamicSharedMemorySize, CV_SMEM);

    // order: 4th launch (ncu capture slot) = conv_fast<stage3> (conv3) this round
    wpack_all_kernel<<<(W2P_TOTAL + W3P_TOTAL + 255) / 256, 256>>>(w2, w3);
    {
        dim3 grid(L1LEN / 64, BATCH);
        conv1_fast_kernel<<<grid, 256>>>(audio, w1, b1);
    }
    {
        dim3 grid(L2LEN / 64, C2 / 128, BATCH);
        conv_fast_kernel<C1, C2, L2LEN, true, false, 2><<<grid, 256, CV_SMEM>>>(b2);
    }
    {
        dim3 grid(L3LEN / 64, HID / 128, BATCH);
        conv_fast_kernel<C2, HID, L3LEN, false, true, 3><<<grid, 256, CV_SMEM>>>(b3);
    }
    split_cb_kernel<<<(KCB * VOCAB * HID) / 256, 256>>>(codebook);
    c2_kernel<<<(KCB * VOCAB) / 8, 256>>>(codebook);
    f2_kernel<<<(BATCH * L3LEN) / 8, 256>>>();
    cbmax_kernel<<<KCB, 256>>>();

    {
        dim3 grid(L3LEN / 128, VOCAB / 128, KCB * BATCH);
        gemm_hi_kernel<<<grid, 256, ST_TOTAL>>>();
    }
    select_kernel<<<NTOK / 8, 256>>>(codebook);

    const int TOK = NTOK;
    const int EMB = BATCH * L3LEN * HID;
    float* out = (float*)d_out;
    if (out_size >= TOK + EMB) {
        tok2f_kernel<<<(TOK + 255) / 256, 256>>>(out);
        emb_kernel<<<BATCH * L3LEN, 128>>>(embedding, out + TOK);
    } else if (out_size >= EMB) {
        emb_kernel<<<BATCH * L3LEN, 128>>>(embedding, out);
    } else {
        tok2f_kernel<<<(TOK + 255) / 256, 256>>>(out);
    }
}